// round 3
// baseline (speedup 1.0000x reference)
#include <cuda_runtime.h>
#include <cuda_bf16.h>
#include <math.h>

#define N_NODES 50000
#define N_EDGES 800000
#define D 256
#define F 64
#define LN_EPS 1e-5f
#define TE 64
#define TN 64

// ---------------- device scratch (no allocations allowed) ----------------
__device__ float g_We1T[F * D];              // [k][d]  transposed W_e1
__device__ float g_WcT[D * D];               // [k][d]  transposed (W_le @ W_e2)
__device__ float g_bc[D];                    // W_le @ b_e2
__device__ float g_Wg1T[D * D];              // [k][d]
__device__ float g_Wg2T[D * D];              // [k][d]
__device__ __align__(16) float g_aggr[(size_t)N_NODES * D];
__device__ int g_idx_is64;                   // 1 if edge_index buffer is int64
__device__ int g_srcs[N_EDGES];              // canonical int32 indices
__device__ int g_dsts[N_EDGES];

// ---------------- helpers ----------------
__device__ __forceinline__ void red_add_v4(float* p, float4 v) {
    asm volatile("red.global.add.v4.f32 [%0], {%1,%2,%3,%4};"
                 :: "l"(p), "f"(v.x), "f"(v.y), "f"(v.z), "f"(v.w)
                 : "memory");
}

// ---------------- index dtype detection + canonicalization ----------------
// If the buffer holds little-endian int64 values < 2^31, every odd int32 word
// is zero. For genuine int32 data (random in [0,50000)), the OR over 1024 odd
// words is nonzero with overwhelming probability. Reads only the first 8 KB,
// safe under both interpretations.
__global__ void detect_idx_kernel(const int* __restrict__ p) {
    __shared__ int acc[256];
    int t = threadIdx.x;                 // 256 threads, 4 odd words each
    int v = 0;
    #pragma unroll
    for (int i = 0; i < 4; i++) v |= p[(t * 4 + i) * 2 + 1];
    acc[t] = v;
    __syncthreads();
    for (int s = 128; s; s >>= 1) {
        if (t < s) acc[t] |= acc[t + s];
        __syncthreads();
    }
    if (t == 0) g_idx_is64 = (acc[0] == 0) ? 1 : 0;
}

__global__ void convert_idx_kernel(const void* __restrict__ eidx) {
    int i = blockIdx.x * blockDim.x + threadIdx.x;
    if (i >= N_EDGES) return;
    int s, d;
    if (g_idx_is64) {
        const long long* p = (const long long*)eidx;
        s = (int)p[i];
        d = (int)p[(size_t)N_EDGES + i];
    } else {
        const int* p = (const int*)eidx;
        s = p[i];
        d = p[N_EDGES + i];
    }
    // defensive clamp: an index surprise becomes rel_err, not an IMA
    s = min(max(s, 0), N_NODES - 1);
    d = min(max(d, 0), N_NODES - 1);
    g_srcs[i] = s;
    g_dsts[i] = d;
}

// ---------------- prep kernels ----------------
__global__ void prep_We1T(const float* __restrict__ W_e1) {
    int k = blockIdx.x, d = threadIdx.x;            // grid F, block D
    g_We1T[k * D + d] = W_e1[d * F + k];
}

__global__ void prep_WcT(const float* __restrict__ W_le,
                         const float* __restrict__ W_e2) {
    int k = blockIdx.x, d = threadIdx.x;            // grid D, block D
    float s = 0.f;
    for (int j = 0; j < D; j++) s += W_le[d * D + j] * W_e2[j * D + k];
    g_WcT[k * D + d] = s;
}

__global__ void prep_bc(const float* __restrict__ W_le,
                        const float* __restrict__ b_e2) {
    int d = threadIdx.x;                            // 1 block of D
    float s = 0.f;
    for (int j = 0; j < D; j++) s += W_le[d * D + j] * b_e2[j];
    g_bc[d] = s;
}

__global__ void prep_WgT(const float* __restrict__ W_g1,
                         const float* __restrict__ W_g2) {
    int k = blockIdx.x, d = threadIdx.x;            // grid D, block D
    g_Wg1T[k * D + d] = W_g1[d * D + k];
    g_Wg2T[k * D + d] = W_g2[d * D + k];
}

__global__ void zero_aggr() {
    size_t i = (size_t)blockIdx.x * blockDim.x + threadIdx.x;
    if (i < (size_t)N_NODES * D / 4) {
        float4 z = make_float4(0.f, 0.f, 0.f, 0.f);
        ((float4*)g_aggr)[i] = z;
    }
}

// ---------------- edge kernel ----------------
#define EDGE_SMEM_FLOATS (TE * 66 + TE * 260 + 64 * 256 + 64 + 64 + 64 + 256 + 256 + 256)
#define EDGE_SMEM_BYTES  (EDGE_SMEM_FLOATS * 4)

__global__ __launch_bounds__(256) void edge_kernel(
    const float* __restrict__ x,
    const float* __restrict__ edge_attr,
    const float* __restrict__ b_e1,
    const float* __restrict__ b_le)
{
    extern __shared__ float smem[];
    float* raws = smem;                       // 64*66
    float* h1s  = raws + TE * 66;             // 64*260
    float* Ws   = h1s + TE * 260;             // 64*256
    float* pol  = Ws + 64 * 256;              // 64
    int*   srcs = (int*)(pol + 64);           // 64
    int*   dsts = srcs + 64;                  // 64
    float* bcs  = (float*)(dsts + 64);        // 256
    float* bls  = bcs + 256;                  // 256
    float* be1s = bls + 256;                  // 256

    const int tid = threadIdx.x;
    const int e0 = blockIdx.x * TE;

    for (int i = tid; i < TE * F; i += 256) {
        int e = i >> 6, k = i & 63;
        raws[e * 66 + k] = edge_attr[(size_t)(e0 + e) * 65 + 1 + k];
    }
    if (tid < TE) {
        float p = edge_attr[(size_t)(e0 + tid) * 65];
        p = fminf(fmaxf(p, 0.f), 1.f) + 0.01f;
        pol[tid] = p;
        srcs[tid] = g_srcs[e0 + tid];
        dsts[tid] = g_dsts[e0 + tid];
    }
    bcs[tid]  = g_bc[tid];
    bls[tid]  = b_le[tid];
    be1s[tid] = b_e1[tid];
    for (int i = tid; i < F * D; i += 256) Ws[i] = g_We1T[i];
    __syncthreads();

    const int ti = tid >> 4;     // 0..15 -> edge group
    const int tj = tid & 15;     // 0..15 -> dim lane
    const int eb = ti * 4;       // 4 edges per thread

    float acc[4][16];
    #pragma unroll
    for (int i = 0; i < 4; i++)
        #pragma unroll
        for (int m = 0; m < 16; m++) acc[i][m] = 0.f;

    // ---- GEMM1: h1 = relu(raw @ W_e1^T + b_e1), K=64 ----
    #pragma unroll 4
    for (int k = 0; k < F; k++) {
        float a0 = raws[(eb + 0) * 66 + k];
        float a1 = raws[(eb + 1) * 66 + k];
        float a2 = raws[(eb + 2) * 66 + k];
        float a3 = raws[(eb + 3) * 66 + k];
        const float* wrow = &Ws[k * 256 + tj];
        #pragma unroll
        for (int m = 0; m < 16; m++) {
            float w = wrow[m * 16];
            acc[0][m] += a0 * w;
            acc[1][m] += a1 * w;
            acc[2][m] += a2 * w;
            acc[3][m] += a3 * w;
        }
    }
    #pragma unroll
    for (int i = 0; i < 4; i++)
        #pragma unroll
        for (int m = 0; m < 16; m++) {
            int d = tj + 16 * m;
            h1s[(eb + i) * 260 + d] = fmaxf(acc[i][m] + be1s[d], 0.f);
        }
    __syncthreads();

    // ---- GEMM2: h2 = h1 @ W_c^T, K=256 streamed in 4 chunks ----
    #pragma unroll
    for (int i = 0; i < 4; i++)
        #pragma unroll
        for (int m = 0; m < 16; m++) acc[i][m] = 0.f;

    for (int kc = 0; kc < 4; kc++) {
        for (int i = tid; i < 64 * 256; i += 256) Ws[i] = g_WcT[kc * 64 * 256 + i];
        __syncthreads();
        #pragma unroll 4
        for (int kk = 0; kk < 64; kk++) {
            int k = kc * 64 + kk;
            float a0 = h1s[(eb + 0) * 260 + k];
            float a1 = h1s[(eb + 1) * 260 + k];
            float a2 = h1s[(eb + 2) * 260 + k];
            float a3 = h1s[(eb + 3) * 260 + k];
            const float* wrow = &Ws[kk * 256 + tj];
            #pragma unroll
            for (int m = 0; m < 16; m++) {
                float w = wrow[m * 16];
                acc[0][m] += a0 * w;
                acc[1][m] += a1 * w;
                acc[2][m] += a2 * w;
                acc[3][m] += a3 * w;
            }
        }
        __syncthreads();
    }

    // ---- polarity gate + biases -> edge_emb in h1s ----
    #pragma unroll
    for (int i = 0; i < 4; i++) {
        float p = pol[eb + i];
        #pragma unroll
        for (int m = 0; m < 16; m++) {
            int d = tj + 16 * m;
            h1s[(eb + i) * 260 + d] = p * (acc[i][m] + bcs[d]) + bls[d];
        }
    }

    // ---- prefetch x[src] rows ----
    const int e_sub  = tid >> 6;   // 0..3
    const int lane64 = tid & 63;   // 0..63 -> float4 index
    float4 xv[16];
    #pragma unroll
    for (int g = 0; g < 16; g++) {
        int e = g * 4 + e_sub;
        const float4* xp = (const float4*)(x + (size_t)srcs[e] * D);
        xv[g] = xp[lane64];
    }
    __syncthreads();

    // ---- msg = relu(x[src] + edge_emb); scatter-add into aggr[dst] ----
    #pragma unroll
    for (int g = 0; g < 16; g++) {
        int e = g * 4 + e_sub;
        float4 ee = *(const float4*)&h1s[e * 260 + lane64 * 4];
        float4 m;
        m.x = fmaxf(xv[g].x + ee.x, 0.f);
        m.y = fmaxf(xv[g].y + ee.y, 0.f);
        m.z = fmaxf(xv[g].z + ee.z, 0.f);
        m.w = fmaxf(xv[g].w + ee.w, 0.f);
        float* dp = &g_aggr[(size_t)dsts[e] * D + lane64 * 4];
        red_add_v4(dp, m);
    }
}

// ---------------- node kernel ----------------
#define NODE_SMEM_FLOATS (TN * 260 + TN * 260 + 64 * 256 + 4 * 256)
#define NODE_SMEM_BYTES  (NODE_SMEM_FLOATS * 4)

__global__ __launch_bounds__(256) void node_kernel(
    const float* __restrict__ x,
    const float* __restrict__ b_g1,
    const float* __restrict__ ln_g,
    const float* __restrict__ ln_b,
    const float* __restrict__ b_g2,
    float* __restrict__ out)
{
    extern __shared__ float smem[];
    float* xs  = smem;                 // 64*260
    float* hs  = xs + TN * 260;        // 64*260
    float* Ws  = hs + TN * 260;        // 64*256
    float* bg1 = Ws + 64 * 256;        // 256
    float* lng = bg1 + 256;            // 256
    float* lnb = lng + 256;            // 256
    float* bg2 = lnb + 256;            // 256

    const int tid = threadIdx.x;
    const int n0 = blockIdx.x * TN;

    for (int i = tid; i < TN * D; i += 256) {
        int n = i >> 8, d = i & 255;
        int g = n0 + n;
        float v = 0.f;
        if (g < N_NODES) v = x[(size_t)g * D + d] + g_aggr[(size_t)g * D + d];
        xs[n * 260 + d] = v;
    }
    bg1[tid] = b_g1[tid];
    lng[tid] = ln_g[tid];
    lnb[tid] = ln_b[tid];
    bg2[tid] = b_g2[tid];
    __syncthreads();

    const int ti = tid >> 4;
    const int tj = tid & 15;
    const int eb = ti * 4;

    float acc[4][16];
    #pragma unroll
    for (int i = 0; i < 4; i++)
        #pragma unroll
        for (int m = 0; m < 16; m++) acc[i][m] = 0.f;

    // GEMM1: h = (x+aggr) @ Wg1^T
    for (int kc = 0; kc < 4; kc++) {
        for (int i = tid; i < 64 * 256; i += 256) Ws[i] = g_Wg1T[kc * 64 * 256 + i];
        __syncthreads();
        #pragma unroll 4
        for (int kk = 0; kk < 64; kk++) {
            int k = kc * 64 + kk;
            float a0 = xs[(eb + 0) * 260 + k];
            float a1 = xs[(eb + 1) * 260 + k];
            float a2 = xs[(eb + 2) * 260 + k];
            float a3 = xs[(eb + 3) * 260 + k];
            const float* wrow = &Ws[kk * 256 + tj];
            #pragma unroll
            for (int m = 0; m < 16; m++) {
                float w = wrow[m * 16];
                acc[0][m] += a0 * w;
                acc[1][m] += a1 * w;
                acc[2][m] += a2 * w;
                acc[3][m] += a3 * w;
            }
        }
        __syncthreads();
    }
    #pragma unroll
    for (int i = 0; i < 4; i++)
        #pragma unroll
        for (int m = 0; m < 16; m++) {
            int d = tj + 16 * m;
            hs[(eb + i) * 260 + d] = acc[i][m] + bg1[d];
        }
    __syncthreads();

    // LayerNorm + relu -> xs (GEMM2 input)
    {
        const int w = tid >> 5;
        const int lane = tid & 31;
        for (int rr = 0; rr < 8; rr++) {
            int row = w * 8 + rr;
            float s = 0.f, s2 = 0.f;
            #pragma unroll
            for (int c = lane; c < D; c += 32) {
                float v = hs[row * 260 + c];
                s += v; s2 += v * v;
            }
            #pragma unroll
            for (int off = 16; off; off >>= 1) {
                s  += __shfl_xor_sync(0xffffffffu, s,  off);
                s2 += __shfl_xor_sync(0xffffffffu, s2, off);
            }
            float mu = s * (1.f / D);
            float var = s2 * (1.f / D) - mu * mu;
            float rstd = rsqrtf(var + LN_EPS);
            #pragma unroll
            for (int c = lane; c < D; c += 32) {
                float v = (hs[row * 260 + c] - mu) * rstd * lng[c] + lnb[c];
                xs[row * 260 + c] = fmaxf(v, 0.f);
            }
        }
    }
    __syncthreads();

    // GEMM2: out = relu(hn) @ Wg2^T + b_g2
    #pragma unroll
    for (int i = 0; i < 4; i++)
        #pragma unroll
        for (int m = 0; m < 16; m++) acc[i][m] = 0.f;

    for (int kc = 0; kc < 4; kc++) {
        for (int i = tid; i < 64 * 256; i += 256) Ws[i] = g_Wg2T[kc * 64 * 256 + i];
        __syncthreads();
        #pragma unroll 4
        for (int kk = 0; kk < 64; kk++) {
            int k = kc * 64 + kk;
            float a0 = xs[(eb + 0) * 260 + k];
            float a1 = xs[(eb + 1) * 260 + k];
            float a2 = xs[(eb + 2) * 260 + k];
            float a3 = xs[(eb + 3) * 260 + k];
            const float* wrow = &Ws[kk * 256 + tj];
            #pragma unroll
            for (int m = 0; m < 16; m++) {
                float w = wrow[m * 16];
                acc[0][m] += a0 * w;
                acc[1][m] += a1 * w;
                acc[2][m] += a2 * w;
                acc[3][m] += a3 * w;
            }
        }
        __syncthreads();
    }
    #pragma unroll
    for (int i = 0; i < 4; i++) {
        int n = n0 + eb + i;
        if (n < N_NODES) {
            #pragma unroll
            for (int m = 0; m < 16; m++) {
                int d = tj + 16 * m;
                out[(size_t)n * D + d] = acc[i][m] + bg2[d];
            }
        }
    }
}

// ---------------- launch ----------------
extern "C" void kernel_launch(void* const* d_in, const int* in_sizes, int n_in,
                              void* d_out, int out_size)
{
    const float* x         = (const float*)d_in[0];
    const void*  eidx      = d_in[1];               // int32 or int64, detected on-device
    const float* edge_attr = (const float*)d_in[2];
    const float* W_e1      = (const float*)d_in[3];
    const float* b_e1      = (const float*)d_in[4];
    const float* W_e2      = (const float*)d_in[5];
    const float* b_e2      = (const float*)d_in[6];
    const float* W_le      = (const float*)d_in[7];
    const float* b_le      = (const float*)d_in[8];
    const float* W_g1      = (const float*)d_in[9];
    const float* b_g1      = (const float*)d_in[10];
    const float* ln_g      = (const float*)d_in[11];
    const float* ln_b      = (const float*)d_in[12];
    const float* W_g2      = (const float*)d_in[13];
    const float* b_g2      = (const float*)d_in[14];
    float*       out       = (float*)d_out;

    cudaFuncSetAttribute(edge_kernel, cudaFuncAttributeMaxDynamicSharedMemorySize, EDGE_SMEM_BYTES);
    cudaFuncSetAttribute(node_kernel, cudaFuncAttributeMaxDynamicSharedMemorySize, NODE_SMEM_BYTES);

    detect_idx_kernel<<<1, 256>>>((const int*)eidx);
    convert_idx_kernel<<<(N_EDGES + 255) / 256, 256>>>(eidx);

    prep_We1T<<<F, D>>>(W_e1);
    prep_WcT<<<D, D>>>(W_le, W_e2);
    prep_bc<<<1, D>>>(W_le, b_e2);
    prep_WgT<<<D, D>>>(W_g1, W_g2);
    zero_aggr<<<(N_NODES * D / 4 + 255) / 256, 256>>>();

    edge_kernel<<<N_EDGES / TE, 256, EDGE_SMEM_BYTES>>>(x, edge_attr, b_e1, b_le);
    node_kernel<<<(N_NODES + TN - 1) / TN, 256, NODE_SMEM_BYTES>>>(x, b_g1, ln_g, ln_b, b_g2, out);
}

// round 4
// speedup vs baseline: 2.3459x; 2.3459x over previous
#include <cuda_runtime.h>
#include <cuda_bf16.h>
#include <math.h>
#include <stdint.h>

#define N_NODES 50000
#define N_EDGES 800000
#define D 256
#define F 64
#define LN_EPS 1e-5f
#define TE 64
#define TN 64

// ---------------- device scratch ----------------
__device__ float g_Wc[D * D];                          // fp32 (W_le @ W_e2), [d][k]
__device__ float g_bc[D];                              // W_le @ b_e2
__device__ __nv_bfloat16 g_We1_h[D * F], g_We1_l[D * F];   // [d][k]
__device__ __nv_bfloat16 g_Wc_h[D * D],  g_Wc_l[D * D];
__device__ __nv_bfloat16 g_Wg1_h[D * D], g_Wg1_l[D * D];
__device__ __nv_bfloat16 g_Wg2_h[D * D], g_Wg2_l[D * D];
__device__ __align__(16) float g_aggr[(size_t)N_NODES * D];
__device__ int g_idx_is64;
__device__ int g_srcs[N_EDGES];
__device__ int g_dsts[N_EDGES];

// ---------------- low-level helpers ----------------
__device__ __forceinline__ void red_add_v4(float* p, float4 v) {
    asm volatile("red.global.add.v4.f32 [%0], {%1,%2,%3,%4};"
                 :: "l"(p), "f"(v.x), "f"(v.y), "f"(v.z), "f"(v.w) : "memory");
}
__device__ __forceinline__ uint32_t smem_u32(const void* p) {
    return (uint32_t)__cvta_generic_to_shared(p);
}
__device__ __forceinline__ void cpasync16(uint32_t dst, const void* src) {
    asm volatile("cp.async.cg.shared.global [%0], [%1], 16;" :: "r"(dst), "l"(src));
}
__device__ __forceinline__ void cp_commit() { asm volatile("cp.async.commit_group;"); }
__device__ __forceinline__ void cp_wait0()  { asm volatile("cp.async.wait_group 0;"); }

__device__ __forceinline__ void ldsm4(uint32_t* r, uint32_t addr) {
    asm volatile("ldmatrix.sync.aligned.m8n8.x4.shared.b16 {%0,%1,%2,%3}, [%4];"
                 : "=r"(r[0]), "=r"(r[1]), "=r"(r[2]), "=r"(r[3]) : "r"(addr));
}
__device__ __forceinline__ void mma_bf16(float* c,
    uint32_t a0, uint32_t a1, uint32_t a2, uint32_t a3, uint32_t b0, uint32_t b1) {
    asm volatile("mma.sync.aligned.m16n8k16.row.col.f32.bf16.bf16.f32 "
                 "{%0,%1,%2,%3}, {%4,%5,%6,%7}, {%8,%9}, {%0,%1,%2,%3};"
                 : "+f"(c[0]), "+f"(c[1]), "+f"(c[2]), "+f"(c[3])
                 : "r"(a0), "r"(a1), "r"(a2), "r"(a3), "r"(b0), "r"(b1));
}
__device__ __forceinline__ void splitpack(float a, float b, uint32_t& hi, uint32_t& lo) {
    __nv_bfloat16 ha = __float2bfloat16_rn(a), hb = __float2bfloat16_rn(b);
    __nv_bfloat16 la = __float2bfloat16_rn(a - __bfloat162float(ha));
    __nv_bfloat16 lb = __float2bfloat16_rn(b - __bfloat162float(hb));
    hi = (uint32_t)__bfloat16_as_ushort(ha) | ((uint32_t)__bfloat16_as_ushort(hb) << 16);
    lo = (uint32_t)__bfloat16_as_ushort(la) | ((uint32_t)__bfloat16_as_ushort(lb) << 16);
}

// B chunk prefetch: [256 n][32 k] bf16 hi+lo -> smem [2][256][40]
__device__ __forceinline__ void prefetch_B(
    const __nv_bfloat16* __restrict__ Gh, const __nv_bfloat16* __restrict__ Gl,
    int gstride, int kofs, uint32_t b_base, int tid)
{
    #pragma unroll
    for (int t = 0; t < 8; t++) {
        int idx = tid + t * 256;
        int h = idx >> 10, rem = idx & 1023, n = rem >> 2, g = rem & 3;
        const __nv_bfloat16* src = (h ? Gl : Gh) + n * gstride + kofs + g * 8;
        uint32_t dst = b_base + (uint32_t)(h * (256 * 40) + n * 40 + g * 8) * 2;
        cpasync16(dst, src);
    }
    cp_commit();
}

// One 32-k chunk of split-bf16 MMA: acc += A_hi*B_hi + A_hi*B_lo + A_lo*B_hi
__device__ __forceinline__ void gemm_chunk(
    float acc[4][4][4],
    uint32_t a_hi_base, uint32_t a_lo_base, int a_stride, int a_kofs,
    const __nv_bfloat16* __restrict__ Bh, const __nv_bfloat16* __restrict__ Bl,
    int lane, int nb)
{
    #pragma unroll
    for (int ks = 0; ks < 2; ks++) {
        int kA = a_kofs + ks * 16;
        uint32_t ahi[4][4], alo[4][4];
        #pragma unroll
        for (int mi = 0; mi < 4; mi++) {
            uint32_t row = mi * 16 + (lane & 15);
            uint32_t col = kA + ((lane >> 4) << 3);
            ldsm4(ahi[mi], a_hi_base + (row * a_stride + col) * 2);
            ldsm4(alo[mi], a_lo_base + (row * a_stride + col) * 2);
        }
        int kB = ks * 16 + (lane & 3) * 2;
        int nr = nb + (lane >> 2);
        uint32_t bh[4][2], bl[4][2];
        #pragma unroll
        for (int ni = 0; ni < 4; ni++) {
            const __nv_bfloat16* ph = Bh + (nr + ni * 8) * 40 + kB;
            const __nv_bfloat16* pl = Bl + (nr + ni * 8) * 40 + kB;
            bh[ni][0] = *(const uint32_t*)ph;      bh[ni][1] = *(const uint32_t*)(ph + 8);
            bl[ni][0] = *(const uint32_t*)pl;      bl[ni][1] = *(const uint32_t*)(pl + 8);
        }
        #pragma unroll
        for (int mi = 0; mi < 4; mi++)
            #pragma unroll
            for (int ni = 0; ni < 4; ni++) {
                mma_bf16(acc[mi][ni], ahi[mi][0], ahi[mi][1], ahi[mi][2], ahi[mi][3], bh[ni][0], bh[ni][1]);
                mma_bf16(acc[mi][ni], ahi[mi][0], ahi[mi][1], ahi[mi][2], ahi[mi][3], bl[ni][0], bl[ni][1]);
                mma_bf16(acc[mi][ni], alo[mi][0], alo[mi][1], alo[mi][2], alo[mi][3], bh[ni][0], bh[ni][1]);
            }
    }
}

// ---------------- index handling (unchanged, proven) ----------------
__global__ void detect_idx_kernel(const int* __restrict__ p) {
    __shared__ int acc[256];
    int t = threadIdx.x;
    int v = 0;
    #pragma unroll
    for (int i = 0; i < 4; i++) v |= p[(t * 4 + i) * 2 + 1];
    acc[t] = v;
    __syncthreads();
    for (int s = 128; s; s >>= 1) { if (t < s) acc[t] |= acc[t + s]; __syncthreads(); }
    if (t == 0) g_idx_is64 = (acc[0] == 0) ? 1 : 0;
}
__global__ void convert_idx_kernel(const void* __restrict__ eidx) {
    int i = blockIdx.x * blockDim.x + threadIdx.x;
    if (i >= N_EDGES) return;
    int s, d;
    if (g_idx_is64) {
        const long long* p = (const long long*)eidx;
        s = (int)p[i]; d = (int)p[(size_t)N_EDGES + i];
    } else {
        const int* p = (const int*)eidx;
        s = p[i]; d = p[N_EDGES + i];
    }
    g_srcs[i] = min(max(s, 0), N_NODES - 1);
    g_dsts[i] = min(max(d, 0), N_NODES - 1);
}

// ---------------- prep kernels ----------------
__global__ void prep_Wc(const float* __restrict__ W_le, const float* __restrict__ W_e2) {
    __shared__ float row[D];
    int d = blockIdx.x, k = threadIdx.x;
    row[k] = W_le[d * D + k];
    __syncthreads();
    float s = 0.f;
    #pragma unroll 4
    for (int j = 0; j < D; j++) s += row[j] * W_e2[j * D + k];
    g_Wc[d * D + k] = s;
}
__global__ void prep_bc(const float* __restrict__ W_le, const float* __restrict__ b_e2) {
    __shared__ float bv[D];
    int d = blockIdx.x, k = threadIdx.x;   // grid D blocks? use 1 block below
    (void)d;
    bv[k] = b_e2[k];
    __syncthreads();
    float s = 0.f;
    for (int j = 0; j < D; j++) s += W_le[threadIdx.x * D + j] * bv[j];
    g_bc[threadIdx.x] = s;
}
__global__ void split_weights(const float* __restrict__ W_e1,
                              const float* __restrict__ W_g1,
                              const float* __restrict__ W_g2) {
    int i = blockIdx.x * 256 + threadIdx.x;   // 832 blocks * 256 = 212992
    float v; __nv_bfloat16 *dh, *dl; int j;
    if (i < D * F)                        { j = i;                 v = W_e1[j]; dh = g_We1_h; dl = g_We1_l; }
    else if (i < D * F + D * D)           { j = i - D * F;         v = g_Wc[j]; dh = g_Wc_h;  dl = g_Wc_l; }
    else if (i < D * F + 2 * D * D)       { j = i - D * F - D * D; v = W_g1[j]; dh = g_Wg1_h; dl = g_Wg1_l; }
    else                                  { j = i - D * F - 2 * D * D; v = W_g2[j]; dh = g_Wg2_h; dl = g_Wg2_l; }
    __nv_bfloat16 h = __float2bfloat16_rn(v);
    dh[j] = h;
    dl[j] = __float2bfloat16_rn(v - __bfloat162float(h));
}
__global__ void zero_aggr() {
    size_t i = (size_t)blockIdx.x * blockDim.x + threadIdx.x;
    if (i < (size_t)N_NODES * D / 4)
        ((float4*)g_aggr)[i] = make_float4(0.f, 0.f, 0.f, 0.f);
}

// ---------------- edge kernel ----------------
// smem byte offsets
#define E_A1H 0
#define E_A1L 9216
#define E_A2H 18432
#define E_A2L 52224
#define E_B   86016
#define E_SML 167936
#define EDGE_SMEM_BYTES 171776

__global__ __launch_bounds__(256, 1) void edge_kernel(
    const float* __restrict__ x,
    const float* __restrict__ edge_attr,
    const float* __restrict__ b_e1,
    const float* __restrict__ b_le)
{
    extern __shared__ char smem[];
    __nv_bfloat16* A1h = (__nv_bfloat16*)(smem + E_A1H);   // [64][72]
    __nv_bfloat16* A1l = (__nv_bfloat16*)(smem + E_A1L);
    __nv_bfloat16* A2h = (__nv_bfloat16*)(smem + E_A2H);   // [64][264]
    __nv_bfloat16* A2l = (__nv_bfloat16*)(smem + E_A2L);
    float* emb  = (float*)(smem + E_B);                    // [64][260] (aliases B)
    float* pol  = (float*)(smem + E_SML);                  // 64
    int*   srcs = (int*)(smem + E_SML + 256);              // 64
    int*   dsts = (int*)(smem + E_SML + 512);              // 64
    float* bcs  = (float*)(smem + E_SML + 768);            // 256
    float* bls  = (float*)(smem + E_SML + 1792);           // 256
    float* be1s = (float*)(smem + E_SML + 2816);           // 256

    const int tid = threadIdx.x;
    const int lane = tid & 31;
    const int warp = tid >> 5;
    const int nb = warp * 32;
    const int e0 = blockIdx.x * TE;
    const uint32_t a1h_u = smem_u32(A1h), a1l_u = smem_u32(A1l);
    const uint32_t a2h_u = smem_u32(A2h), a2l_u = smem_u32(A2l);

    // stage raw split A1
    for (int i = tid; i < TE * F; i += 256) {
        int e = i >> 6, k = i & 63;
        float v = edge_attr[(size_t)(e0 + e) * 65 + 1 + k];
        __nv_bfloat16 h = __float2bfloat16_rn(v);
        A1h[e * 72 + k] = h;
        A1l[e * 72 + k] = __float2bfloat16_rn(v - __bfloat162float(h));
    }
    if (tid < TE) {
        float p = edge_attr[(size_t)(e0 + tid) * 65];
        pol[tid] = fminf(fmaxf(p, 0.f), 1.f) + 0.01f;
        srcs[tid] = g_srcs[e0 + tid];
        dsts[tid] = g_dsts[e0 + tid];
    }
    bcs[tid]  = g_bc[tid];
    bls[tid]  = b_le[tid];
    be1s[tid] = b_e1[tid];

    prefetch_B(g_We1_h, g_We1_l, F, 0, smem_u32(smem + E_B), tid);  // GEMM1 chunk0 -> buf0
    __syncthreads();

    float acc[4][4][4];
    #pragma unroll
    for (int a = 0; a < 4; a++)
        #pragma unroll
        for (int b = 0; b < 4; b++)
            #pragma unroll
            for (int c = 0; c < 4; c++) acc[a][b][c] = 0.f;

    // ---- GEMM1: h1 = relu(raw @ We1^T + b_e1), 2 chunks ----
    #pragma unroll
    for (int kc = 0; kc < 2; kc++) {
        cp_wait0();
        __syncthreads();
        if (kc == 0)
            prefetch_B(g_We1_h, g_We1_l, F, 32, smem_u32(smem + E_B + 40960), tid);
        else
            prefetch_B(g_Wc_h, g_Wc_l, D, 0, smem_u32(smem + E_B), tid);   // GEMM2 chunk0 -> buf0
        const __nv_bfloat16* Bh = (const __nv_bfloat16*)(smem + E_B + (kc & 1) * 40960);
        gemm_chunk(acc, a1h_u, a1l_u, 72, kc * 32, Bh, Bh + 256 * 40, lane, nb);
    }

    // GEMM1 epilogue -> split into A2
    {
        int r = lane >> 2, cb = (lane & 3) * 2;
        #pragma unroll
        for (int mi = 0; mi < 4; mi++)
            #pragma unroll
            for (int ni = 0; ni < 4; ni++) {
                int col = nb + ni * 8 + cb;
                int r0 = mi * 16 + r, r1 = r0 + 8;
                float v00 = fmaxf(acc[mi][ni][0] + be1s[col], 0.f);
                float v01 = fmaxf(acc[mi][ni][1] + be1s[col + 1], 0.f);
                float v10 = fmaxf(acc[mi][ni][2] + be1s[col], 0.f);
                float v11 = fmaxf(acc[mi][ni][3] + be1s[col + 1], 0.f);
                uint32_t hi, lo;
                splitpack(v00, v01, hi, lo);
                *(uint32_t*)&A2h[r0 * 264 + col] = hi;
                *(uint32_t*)&A2l[r0 * 264 + col] = lo;
                splitpack(v10, v11, hi, lo);
                *(uint32_t*)&A2h[r1 * 264 + col] = hi;
                *(uint32_t*)&A2l[r1 * 264 + col] = lo;
                acc[mi][ni][0] = acc[mi][ni][1] = acc[mi][ni][2] = acc[mi][ni][3] = 0.f;
            }
    }
    __syncthreads();

    // ---- GEMM2: h2 = h1 @ Wc^T, 8 chunks ----
    #pragma unroll 1
    for (int kc = 0; kc < 8; kc++) {
        cp_wait0();
        __syncthreads();
        if (kc < 7)
            prefetch_B(g_Wc_h, g_Wc_l, D, (kc + 1) * 32,
                       smem_u32(smem + E_B + ((kc + 1) & 1) * 40960), tid);
        const __nv_bfloat16* Bh = (const __nv_bfloat16*)(smem + E_B + (kc & 1) * 40960);
        gemm_chunk(acc, a2h_u, a2l_u, 264, kc * 32, Bh, Bh + 256 * 40, lane, nb);
    }
    __syncthreads();   // all B reads done; emb may alias B now

    // GEMM2 epilogue: edge_emb = pol*(h2 + bc) + bl  -> emb smem
    {
        int r = lane >> 2, cb = (lane & 3) * 2;
        #pragma unroll
        for (int mi = 0; mi < 4; mi++)
            #pragma unroll
            for (int ni = 0; ni < 4; ni++) {
                int col = nb + ni * 8 + cb;
                int r0 = mi * 16 + r, r1 = r0 + 8;
                float p0 = pol[r0], p1 = pol[r1];
                float2 v0 = make_float2(p0 * (acc[mi][ni][0] + bcs[col]) + bls[col],
                                        p0 * (acc[mi][ni][1] + bcs[col + 1]) + bls[col + 1]);
                float2 v1 = make_float2(p1 * (acc[mi][ni][2] + bcs[col]) + bls[col],
                                        p1 * (acc[mi][ni][3] + bcs[col + 1]) + bls[col + 1]);
                *(float2*)&emb[r0 * 260 + col] = v0;
                *(float2*)&emb[r1 * 260 + col] = v1;
            }
    }
    __syncthreads();

    // ---- gather x[src], msg = relu(x+emb), scatter-add ----
    const int e_sub  = tid >> 6;
    const int lane64 = tid & 63;
    #pragma unroll
    for (int g = 0; g < 16; g++) {
        int e = g * 4 + e_sub;
        const float4* xp = (const float4*)(x + (size_t)srcs[e] * D);
        float4 xv = xp[lane64];
        float4 ee = *(const float4*)&emb[e * 260 + lane64 * 4];
        float4 m;
        m.x = fmaxf(xv.x + ee.x, 0.f);
        m.y = fmaxf(xv.y + ee.y, 0.f);
        m.z = fmaxf(xv.z + ee.z, 0.f);
        m.w = fmaxf(xv.w + ee.w, 0.f);
        red_add_v4(&g_aggr[(size_t)dsts[e] * D + lane64 * 4], m);
    }
}

// ---------------- node kernel ----------------
#define N_AH  0
#define N_AL  33792
#define N_B   67584
#define N_SML 149504
#define NODE_SMEM_BYTES 153600

__global__ __launch_bounds__(256, 1) void node_kernel(
    const float* __restrict__ x,
    const float* __restrict__ b_g1,
    const float* __restrict__ ln_g,
    const float* __restrict__ ln_b,
    const float* __restrict__ b_g2,
    float* __restrict__ out)
{
    extern __shared__ char smem[];
    __nv_bfloat16* Ah = (__nv_bfloat16*)(smem + N_AH);   // [64][264]
    __nv_bfloat16* Al = (__nv_bfloat16*)(smem + N_AL);
    float* hbuf = (float*)(smem + N_B);                  // [64][260] aliases B
    float* bg1 = (float*)(smem + N_SML);
    float* lng = (float*)(smem + N_SML + 1024);
    float* lnb = (float*)(smem + N_SML + 2048);
    float* bg2 = (float*)(smem + N_SML + 3072);

    const int tid = threadIdx.x;
    const int lane = tid & 31;
    const int warp = tid >> 5;
    const int nb = warp * 32;
    const int n0 = blockIdx.x * TN;
    const uint32_t ah_u = smem_u32(Ah), al_u = smem_u32(Al);

    // stage xin = x + aggr, split
    for (int i = tid; i < TN * D; i += 256) {
        int n = i >> 8, d = i & 255;
        int g = n0 + n;
        float v = 0.f;
        if (g < N_NODES) v = x[(size_t)g * D + d] + g_aggr[(size_t)g * D + d];
        __nv_bfloat16 h = __float2bfloat16_rn(v);
        Ah[n * 264 + d] = h;
        Al[n * 264 + d] = __float2bfloat16_rn(v - __bfloat162float(h));
    }
    bg1[tid] = b_g1[tid];
    lng[tid] = ln_g[tid];
    lnb[tid] = ln_b[tid];
    bg2[tid] = b_g2[tid];

    prefetch_B(g_Wg1_h, g_Wg1_l, D, 0, smem_u32(smem + N_B), tid);
    __syncthreads();

    float acc[4][4][4];
    #pragma unroll
    for (int a = 0; a < 4; a++)
        #pragma unroll
        for (int b = 0; b < 4; b++)
            #pragma unroll
            for (int c = 0; c < 4; c++) acc[a][b][c] = 0.f;

    // GEMM1
    #pragma unroll 1
    for (int kc = 0; kc < 8; kc++) {
        cp_wait0();
        __syncthreads();
        if (kc < 7)
            prefetch_B(g_Wg1_h, g_Wg1_l, D, (kc + 1) * 32,
                       smem_u32(smem + N_B + ((kc + 1) & 1) * 40960), tid);
        const __nv_bfloat16* Bh = (const __nv_bfloat16*)(smem + N_B + (kc & 1) * 40960);
        gemm_chunk(acc, ah_u, al_u, 264, kc * 32, Bh, Bh + 256 * 40, lane, nb);
    }
    __syncthreads();

    // epilogue: h = acc + bg1 -> hbuf (aliases B)
    {
        int r = lane >> 2, cb = (lane & 3) * 2;
        #pragma unroll
        for (int mi = 0; mi < 4; mi++)
            #pragma unroll
            for (int ni = 0; ni < 4; ni++) {
                int col = nb + ni * 8 + cb;
                int r0 = mi * 16 + r, r1 = r0 + 8;
                *(float2*)&hbuf[r0 * 260 + col] =
                    make_float2(acc[mi][ni][0] + bg1[col], acc[mi][ni][1] + bg1[col + 1]);
                *(float2*)&hbuf[r1 * 260 + col] =
                    make_float2(acc[mi][ni][2] + bg1[col], acc[mi][ni][3] + bg1[col + 1]);
                acc[mi][ni][0] = acc[mi][ni][1] = acc[mi][ni][2] = acc[mi][ni][3] = 0.f;
            }
    }
    __syncthreads();

    // LayerNorm + relu -> split into A (GEMM2 input)
    {
        for (int rr = 0; rr < 8; rr++) {
            int row = warp * 8 + rr;
            float s = 0.f, s2 = 0.f;
            #pragma unroll
            for (int c = lane; c < D; c += 32) {
                float v = hbuf[row * 260 + c];
                s += v; s2 += v * v;
            }
            #pragma unroll
            for (int off = 16; off; off >>= 1) {
                s  += __shfl_xor_sync(0xffffffffu, s,  off);
                s2 += __shfl_xor_sync(0xffffffffu, s2, off);
            }
            float mu = s * (1.f / D);
            float var = s2 * (1.f / D) - mu * mu;
            float rstd = rsqrtf(var + LN_EPS);
            #pragma unroll
            for (int c = lane; c < D; c += 32) {
                float v = (hbuf[row * 260 + c] - mu) * rstd * lng[c] + lnb[c];
                v = fmaxf(v, 0.f);
                __nv_bfloat16 h = __float2bfloat16_rn(v);
                Ah[row * 264 + c] = h;
                Al[row * 264 + c] = __float2bfloat16_rn(v - __bfloat162float(h));
            }
        }
    }
    __syncthreads();

    prefetch_B(g_Wg2_h, g_Wg2_l, D, 0, smem_u32(smem + N_B), tid);

    // GEMM2
    #pragma unroll 1
    for (int kc = 0; kc < 8; kc++) {
        cp_wait0();
        __syncthreads();
        if (kc < 7)
            prefetch_B(g_Wg2_h, g_Wg2_l, D, (kc + 1) * 32,
                       smem_u32(smem + N_B + ((kc + 1) & 1) * 40960), tid);
        const __nv_bfloat16* Bh = (const __nv_bfloat16*)(smem + N_B + (kc & 1) * 40960);
        gemm_chunk(acc, ah_u, al_u, 264, kc * 32, Bh, Bh + 256 * 40, lane, nb);
    }

    // final epilogue -> out
    {
        int r = lane >> 2, cb = (lane & 3) * 2;
        #pragma unroll
        for (int mi = 0; mi < 4; mi++)
            #pragma unroll
            for (int ni = 0; ni < 4; ni++) {
                int col = nb + ni * 8 + cb;
                int r0 = mi * 16 + r, r1 = r0 + 8;
                int gr0 = n0 + r0, gr1 = n0 + r1;
                if (gr0 < N_NODES)
                    *(float2*)&out[(size_t)gr0 * D + col] =
                        make_float2(acc[mi][ni][0] + bg2[col], acc[mi][ni][1] + bg2[col + 1]);
                if (gr1 < N_NODES)
                    *(float2*)&out[(size_t)gr1 * D + col] =
                        make_float2(acc[mi][ni][2] + bg2[col], acc[mi][ni][3] + bg2[col + 1]);
            }
    }
}

// ---------------- launch ----------------
extern "C" void kernel_launch(void* const* d_in, const int* in_sizes, int n_in,
                              void* d_out, int out_size)
{
    const float* x         = (const float*)d_in[0];
    const void*  eidx      = d_in[1];
    const float* edge_attr = (const float*)d_in[2];
    const float* W_e1      = (const float*)d_in[3];
    const float* b_e1      = (const float*)d_in[4];
    const float* W_e2      = (const float*)d_in[5];
    const float* b_e2      = (const float*)d_in[6];
    const float* W_le      = (const float*)d_in[7];
    const float* b_le      = (const float*)d_in[8];
    const float* W_g1      = (const float*)d_in[9];
    const float* b_g1      = (const float*)d_in[10];
    const float* ln_g      = (const float*)d_in[11];
    const float* ln_b      = (const float*)d_in[12];
    const float* W_g2      = (const float*)d_in[13];
    const float* b_g2      = (const float*)d_in[14];
    float*       out       = (float*)d_out;

    cudaFuncSetAttribute(edge_kernel, cudaFuncAttributeMaxDynamicSharedMemorySize, EDGE_SMEM_BYTES);
    cudaFuncSetAttribute(node_kernel, cudaFuncAttributeMaxDynamicSharedMemorySize, NODE_SMEM_BYTES);

    detect_idx_kernel<<<1, 256>>>((const int*)eidx);
    convert_idx_kernel<<<(N_EDGES + 255) / 256, 256>>>(eidx);

    prep_Wc<<<D, D>>>(W_le, W_e2);
    prep_bc<<<1, D>>>(W_le, b_e2);
    split_weights<<<832, 256>>>(W_e1, W_g1, W_g2);
    zero_aggr<<<(N_NODES * D / 4 + 255) / 256, 256>>>();

    edge_kernel<<<N_EDGES / TE, 256, EDGE_SMEM_BYTES>>>(x, edge_attr, b_e1, b_le);
    node_kernel<<<(N_NODES + TN - 1) / TN, 256, NODE_SMEM_BYTES>>>(x, b_g1, ln_g, ln_b, b_g2, out);
}

// round 5
// speedup vs baseline: 3.5172x; 1.4993x over previous
#include <cuda_runtime.h>
#include <cuda_bf16.h>
#include <stdint.h>

#define N_NODES 50000
#define N_EDGES 800000
#define D 256
#define F 64
#define LN_EPS 1e-5f

// ---------------- device scratch ----------------
__device__ float g_Wc[D * D];                              // (W_le @ W_e2)  [d][k]
__device__ float g_bc[D];                                  // W_le @ b_e2
__device__ __nv_bfloat16 g_We1_h[D * F], g_We1_l[D * F];   // [n][k]
__device__ __nv_bfloat16 g_Wc_h[D * D],  g_Wc_l[D * D];
__device__ __nv_bfloat16 g_Wg1_h[D * D], g_Wg1_l[D * D];
__device__ __nv_bfloat16 g_Wg2_h[D * D], g_Wg2_l[D * D];
__device__ __align__(16) float g_aggr[(size_t)N_NODES * D];
__device__ int g_idx_is64;
__device__ int g_srcs[N_EDGES], g_dsts[N_EDGES];

// ---------------- low-level helpers ----------------
__device__ __forceinline__ void red_add_v4(float* p, float4 v) {
    asm volatile("red.global.add.v4.f32 [%0], {%1,%2,%3,%4};"
                 :: "l"(p), "f"(v.x), "f"(v.y), "f"(v.z), "f"(v.w) : "memory");
}
__device__ __forceinline__ uint32_t smem_u32(const void* p) {
    return (uint32_t)__cvta_generic_to_shared(p);
}
__device__ __forceinline__ void cpasync16(uint32_t dst, const void* src) {
    asm volatile("cp.async.cg.shared.global [%0], [%1], 16;" :: "r"(dst), "l"(src));
}
__device__ __forceinline__ void cp_commit() { asm volatile("cp.async.commit_group;"); }
__device__ __forceinline__ void cp_wait0()  { asm volatile("cp.async.wait_group 0;"); }

__device__ __forceinline__ void ldsm4(uint32_t* r, uint32_t addr) {
    asm volatile("ldmatrix.sync.aligned.m8n8.x4.shared.b16 {%0,%1,%2,%3}, [%4];"
                 : "=r"(r[0]), "=r"(r[1]), "=r"(r[2]), "=r"(r[3]) : "r"(addr));
}
__device__ __forceinline__ void mma_bf16(float* c,
    uint32_t a0, uint32_t a1, uint32_t a2, uint32_t a3, uint32_t b0, uint32_t b1) {
    asm volatile("mma.sync.aligned.m16n8k16.row.col.f32.bf16.bf16.f32 "
                 "{%0,%1,%2,%3}, {%4,%5,%6,%7}, {%8,%9}, {%0,%1,%2,%3};"
                 : "+f"(c[0]), "+f"(c[1]), "+f"(c[2]), "+f"(c[3])
                 : "r"(a0), "r"(a1), "r"(a2), "r"(a3), "r"(b0), "r"(b1));
}
__device__ __forceinline__ void splitpack(float a, float b, uint32_t& hi, uint32_t& lo) {
    __nv_bfloat16 ha = __float2bfloat16_rn(a), hb = __float2bfloat16_rn(b);
    __nv_bfloat16 la = __float2bfloat16_rn(a - __bfloat162float(ha));
    __nv_bfloat16 lb = __float2bfloat16_rn(b - __bfloat162float(hb));
    hi = (uint32_t)__bfloat16_as_ushort(ha) | ((uint32_t)__bfloat16_as_ushort(hb) << 16);
    lo = (uint32_t)__bfloat16_as_ushort(la) | ((uint32_t)__bfloat16_as_ushort(lb) << 16);
}

// B chunk prefetch: [256 n][32 k] bf16 hi+lo -> smem [2][256][40]
__device__ __forceinline__ void prefetch_B(
    const __nv_bfloat16* __restrict__ Gh, const __nv_bfloat16* __restrict__ Gl,
    int gstride, int kofs, uint32_t b_base, int tid)
{
    #pragma unroll
    for (int t = 0; t < 8; t++) {
        int idx = tid + t * 256;
        int h = idx >> 10, rem = idx & 1023, n = rem >> 2, g = rem & 3;
        const __nv_bfloat16* src = (h ? Gl : Gh) + n * gstride + kofs + g * 8;
        uint32_t dst = b_base + (uint32_t)(h * (256 * 40) + n * 40 + g * 8) * 2;
        cpasync16(dst, src);
    }
    cp_commit();
}

// NI n-tiles of 3-pass split MMA, A fragments given in registers.
template<int NI>
__device__ __forceinline__ void mma_rows(
    float (*acc)[4], const uint32_t* ah, const uint32_t* al,
    const __nv_bfloat16* __restrict__ Bh, const __nv_bfloat16* __restrict__ Bl,
    int ni0, int kB, int lane)
{
    int nr = lane >> 2;
    #pragma unroll
    for (int ni = 0; ni < NI; ni++) {
        const __nv_bfloat16* ph = Bh + ((ni0 + ni) * 8 + nr) * 40 + kB;
        const __nv_bfloat16* pl = Bl + ((ni0 + ni) * 8 + nr) * 40 + kB;
        uint32_t bh0 = *(const uint32_t*)ph, bh1 = *(const uint32_t*)(ph + 8);
        uint32_t bl0 = *(const uint32_t*)pl, bl1 = *(const uint32_t*)(pl + 8);
        mma_bf16(acc[ni], ah[0], ah[1], ah[2], ah[3], bh0, bh1);
        mma_bf16(acc[ni], ah[0], ah[1], ah[2], ah[3], bl0, bl1);
        mma_bf16(acc[ni], al[0], al[1], al[2], al[3], bh0, bh1);
    }
}

// ---------------- index handling (proven) ----------------
__global__ void detect_idx_kernel(const int* __restrict__ p) {
    __shared__ int acc[256];
    int t = threadIdx.x;
    int v = 0;
    #pragma unroll
    for (int i = 0; i < 4; i++) v |= p[(t * 4 + i) * 2 + 1];
    acc[t] = v;
    __syncthreads();
    for (int s = 128; s; s >>= 1) { if (t < s) acc[t] |= acc[t + s]; __syncthreads(); }
    if (t == 0) g_idx_is64 = (acc[0] == 0) ? 1 : 0;
}
__global__ void convert_idx_kernel(const void* __restrict__ eidx) {
    int i = blockIdx.x * blockDim.x + threadIdx.x;
    if (i >= N_EDGES) return;
    int s, d;
    if (g_idx_is64) {
        const long long* p = (const long long*)eidx;
        s = (int)p[i]; d = (int)p[(size_t)N_EDGES + i];
    } else {
        const int* p = (const int*)eidx;
        s = p[i]; d = p[N_EDGES + i];
    }
    g_srcs[i] = min(max(s, 0), N_NODES - 1);
    g_dsts[i] = min(max(d, 0), N_NODES - 1);
}

// ---------------- prep kernels ----------------
__global__ void prep_Wc(const float* __restrict__ W_le, const float* __restrict__ W_e2) {
    __shared__ float wle[4][256];
    int b = blockIdx.x, t = threadIdx.x;       // 64 blocks
    #pragma unroll
    for (int r = 0; r < 4; r++) wle[r][t] = W_le[(b * 4 + r) * 256 + t];
    __syncthreads();
    float a0 = 0, a1 = 0, a2 = 0, a3 = 0;
    #pragma unroll 4
    for (int j = 0; j < 256; j++) {
        float w = W_e2[j * 256 + t];
        a0 += wle[0][j] * w; a1 += wle[1][j] * w;
        a2 += wle[2][j] * w; a3 += wle[3][j] * w;
    }
    g_Wc[(b * 4 + 0) * 256 + t] = a0;
    g_Wc[(b * 4 + 1) * 256 + t] = a1;
    g_Wc[(b * 4 + 2) * 256 + t] = a2;
    g_Wc[(b * 4 + 3) * 256 + t] = a3;
}
__global__ void prep_bc(const float* __restrict__ W_le, const float* __restrict__ b_e2) {
    __shared__ float red[256];
    int d = blockIdx.x, t = threadIdx.x;       // 256 blocks
    red[t] = W_le[d * 256 + t] * b_e2[t];
    __syncthreads();
    for (int s = 128; s; s >>= 1) { if (t < s) red[t] += red[t + s]; __syncthreads(); }
    if (t == 0) g_bc[d] = red[0];
}
__global__ void split_weights(const float* __restrict__ W_e1,
                              const float* __restrict__ W_g1,
                              const float* __restrict__ W_g2) {
    int i = blockIdx.x * 256 + threadIdx.x;
    float v; __nv_bfloat16 *dh, *dl; int j;
    if (i < D * F)                  { j = i;                     v = W_e1[j]; dh = g_We1_h; dl = g_We1_l; }
    else if (i < D * F + D * D)     { j = i - D * F;             v = g_Wc[j]; dh = g_Wc_h;  dl = g_Wc_l; }
    else if (i < D * F + 2 * D * D) { j = i - D * F - D * D;     v = W_g1[j]; dh = g_Wg1_h; dl = g_Wg1_l; }
    else                            { j = i - D * F - 2 * D * D; v = W_g2[j]; dh = g_Wg2_h; dl = g_Wg2_l; }
    __nv_bfloat16 h = __float2bfloat16_rn(v);
    dh[j] = h;
    dl[j] = __float2bfloat16_rn(v - __bfloat162float(h));
}
__global__ void zero_aggr() {
    size_t i = (size_t)blockIdx.x * blockDim.x + threadIdx.x;
    if (i < (size_t)N_NODES * D / 4)
        ((float4*)g_aggr)[i] = make_float4(0.f, 0.f, 0.f, 0.f);
}

// ---------------- edge kernel (128 edges/block, 8 warps, warp = 16 rows) ----------------
#define TE 128
#define E_A1H 0
#define E_A1L 18432
#define E_B   36864      // double buffer, 2 x 40960
#define E_EMB 118784     // [128][136] fp32 = 69632
#define E_SML 188416
#define EDGE_SMEM_BYTES 193024

__global__ __launch_bounds__(256, 1) void edge_kernel(
    const float* __restrict__ x,
    const float* __restrict__ edge_attr,
    const float* __restrict__ b_e1,
    const float* __restrict__ b_le)
{
    extern __shared__ char smem[];
    __nv_bfloat16* A1h = (__nv_bfloat16*)(smem + E_A1H);   // [128][72]
    __nv_bfloat16* A1l = (__nv_bfloat16*)(smem + E_A1L);
    float* embs = (float*)(smem + E_EMB);                  // [128][136]
    float* pol  = (float*)(smem + E_SML);                  // 128
    int*   srcs = (int*)(smem + E_SML + 512);              // 128
    int*   dsts = (int*)(smem + E_SML + 1024);             // 128
    float* bcs  = (float*)(smem + E_SML + 1536);           // 256
    float* bls  = (float*)(smem + E_SML + 2560);           // 256
    float* be1s = (float*)(smem + E_SML + 3584);           // 256

    const int tid  = threadIdx.x;
    const int lane = tid & 31;
    const int warp = tid >> 5;
    const int e0   = blockIdx.x * TE;
    const uint32_t a1h_u = smem_u32(A1h), a1l_u = smem_u32(A1l);
    const uint32_t bbase = smem_u32(smem + E_B);

    prefetch_B(g_We1_h, g_We1_l, F, 0, bbase, tid);   // GEMM1 chunk0 -> buf0

    // stage raw split A1 + metadata
    #pragma unroll
    for (int t = 0; t < 32; t++) {
        int i = tid + t * 256;          // 128*64
        int e = i >> 6, k = i & 63;
        float v = edge_attr[(size_t)(e0 + e) * 65 + 1 + k];
        __nv_bfloat16 h = __float2bfloat16_rn(v);
        A1h[e * 72 + k] = h;
        A1l[e * 72 + k] = __float2bfloat16_rn(v - __bfloat162float(h));
    }
    if (tid < TE) {
        float p = edge_attr[(size_t)(e0 + tid) * 65];
        pol[tid] = fminf(fmaxf(p, 0.f), 1.f) + 0.01f;
        srcs[tid] = g_srcs[e0 + tid];
        dsts[tid] = g_dsts[e0 + tid];
    } else {
        int t2 = tid - 128;   // 128 threads load 256-entry bias arrays (2 each)
        bcs[t2] = g_bc[t2];           bcs[t2 + 128] = g_bc[t2 + 128];
        bls[t2] = b_le[t2];           bls[t2 + 128] = b_le[t2 + 128];
        be1s[t2] = b_e1[t2];          be1s[t2 + 128] = b_e1[t2 + 128];
    }

    // ---- GEMM1: h1 = raw @ We1^T (k=64, 2 chunks), warp owns rows 16w..16w+15, all 256 n ----
    float acc1[32][4];
    #pragma unroll
    for (int n = 0; n < 32; n++)
        #pragma unroll
        for (int j = 0; j < 4; j++) acc1[n][j] = 0.f;

    #pragma unroll
    for (int kc = 0; kc < 2; kc++) {
        cp_wait0();
        __syncthreads();
        if (kc == 0) prefetch_B(g_We1_h, g_We1_l, F, 32, bbase + 40960, tid);
        else         prefetch_B(g_Wc_h,  g_Wc_l,  D, 0,  bbase, tid);        // GEMM2 c0 -> buf0
        const __nv_bfloat16* Bh = (const __nv_bfloat16*)(smem + E_B + kc * 40960);
        const __nv_bfloat16* Bl = Bh + 256 * 40;
        #pragma unroll
        for (int ks = 0; ks < 2; ks++) {
            uint32_t arow = warp * 16 + (lane & 15);
            uint32_t acol = kc * 32 + ks * 16 + ((lane >> 4) << 3);
            uint32_t ah[4], al[4];
            ldsm4(ah, a1h_u + (arow * 72 + acol) * 2);
            ldsm4(al, a1l_u + (arow * 72 + acol) * 2);
            mma_rows<32>(acc1, ah, al, Bh, Bl, 0, ks * 16 + (lane & 3) * 2, lane);
        }
    }

    // ---- h1 = relu(acc1 + b_e1), split in-register into GEMM2 A fragments ----
    uint32_t fh[64], fl[64];
    #pragma unroll
    for (int ni = 0; ni < 32; ni++) {
        int col = ni * 8 + 2 * (lane & 3);
        float2 b = *(const float2*)&be1s[col];
        float v0 = fmaxf(acc1[ni][0] + b.x, 0.f);
        float v1 = fmaxf(acc1[ni][1] + b.y, 0.f);
        float v2 = fmaxf(acc1[ni][2] + b.x, 0.f);
        float v3 = fmaxf(acc1[ni][3] + b.y, 0.f);
        splitpack(v0, v1, fh[2 * ni],     fl[2 * ni]);
        splitpack(v2, v3, fh[2 * ni + 1], fl[2 * ni + 1]);
    }

    const int R0 = warp * 16 + (lane >> 2);
    const int R1 = R0 + 8;

    // ---- GEMM2 (k=256, 8 chunks) in two n-halves; epilogue + scatter per half ----
    #pragma unroll 1
    for (int half = 0; half < 2; half++) {
        float acc2[16][4];
        #pragma unroll
        for (int n = 0; n < 16; n++)
            #pragma unroll
            for (int j = 0; j < 4; j++) acc2[n][j] = 0.f;

        #pragma unroll
        for (int kc = 0; kc < 8; kc++) {
            cp_wait0();
            __syncthreads();
            if (kc < 7)
                prefetch_B(g_Wc_h, g_Wc_l, D, (kc + 1) * 32, bbase + ((kc + 1) & 1) * 40960, tid);
            const __nv_bfloat16* Bh = (const __nv_bfloat16*)(smem + E_B + (kc & 1) * 40960);
            const __nv_bfloat16* Bl = Bh + 256 * 40;
            #pragma unroll
            for (int ks = 0; ks < 2; ks++) {
                int j = kc * 2 + ks;
                mma_rows<16>(acc2, &fh[4 * j], &fl[4 * j], Bh, Bl, half * 16,
                             ks * 16 + (lane & 3) * 2, lane);
            }
        }

        // epilogue: emb = pol*(h2 + bc) + bl -> smem staging
        {
            float p0 = pol[R0], p1 = pol[R1];
            #pragma unroll
            for (int ni = 0; ni < 16; ni++) {
                int col = half * 128 + ni * 8 + 2 * (lane & 3);
                int lc  = col - half * 128;
                float2 bcv = *(const float2*)&bcs[col];
                float2 blv = *(const float2*)&bls[col];
                *(float2*)&embs[R0 * 136 + lc] =
                    make_float2(p0 * (acc2[ni][0] + bcv.x) + blv.x,
                                p0 * (acc2[ni][1] + bcv.y) + blv.y);
                *(float2*)&embs[R1 * 136 + lc] =
                    make_float2(p1 * (acc2[ni][2] + bcv.x) + blv.x,
                                p1 * (acc2[ni][3] + bcv.y) + blv.y);
            }
        }
        __syncthreads();
        if (half == 0)
            prefetch_B(g_Wc_h, g_Wc_l, D, 0, bbase, tid);    // restart chain for half1

        // gather + msg + scatter for this half (warp reads/writes one row span)
        {
            int rg = tid >> 5, c4 = tid & 31;
            #pragma unroll
            for (int it = 0; it < 16; it++) {
                int r = it * 8 + rg;
                float4 ee = *(const float4*)&embs[r * 136 + c4 * 4];
                const float4* xp = (const float4*)(x + (size_t)srcs[r] * D + half * 128);
                float4 xv = xp[c4];
                float4 m;
                m.x = fmaxf(xv.x + ee.x, 0.f);
                m.y = fmaxf(xv.y + ee.y, 0.f);
                m.z = fmaxf(xv.z + ee.z, 0.f);
                m.w = fmaxf(xv.w + ee.w, 0.f);
                red_add_v4(&g_aggr[(size_t)dsts[r] * D + half * 128 + c4 * 4], m);
            }
        }
        // no sync needed here: next half's chunk loop syncs before touching smem B,
        // and emb rewrite happens only after 8 further syncs.
    }
}

// ---------------- node kernel (128 nodes/block) ----------------
#define TN 128
#define N_AH  0
#define N_AL  67584
#define N_B   135168
#define N_SML 217088
#define NODE_SMEM_BYTES 221184

__global__ __launch_bounds__(256, 1) void node_kernel(
    const float* __restrict__ x,
    const float* __restrict__ b_g1,
    const float* __restrict__ ln_g,
    const float* __restrict__ ln_b,
    const float* __restrict__ b_g2,
    float* __restrict__ out)
{
    extern __shared__ char smem[];
    __nv_bfloat16* Ah = (__nv_bfloat16*)(smem + N_AH);   // [128][264]
    __nv_bfloat16* Al = (__nv_bfloat16*)(smem + N_AL);
    float* bg1 = (float*)(smem + N_SML);
    float* lng = (float*)(smem + N_SML + 1024);
    float* lnb = (float*)(smem + N_SML + 2048);
    float* bg2 = (float*)(smem + N_SML + 3072);

    const int tid  = threadIdx.x;
    const int lane = tid & 31;
    const int warp = tid >> 5;
    const int n0   = blockIdx.x * TN;
    const uint32_t ah_u = smem_u32(Ah), al_u = smem_u32(Al);
    const uint32_t bbase = smem_u32(smem + N_B);

    prefetch_B(g_Wg1_h, g_Wg1_l, D, 0, bbase, tid);

    // stage xin = x + aggr, split
    #pragma unroll
    for (int t = 0; t < 128; t++) {
        int i = tid + t * 256;          // 128*256
        int n = i >> 8, d = i & 255;
        int g = n0 + n;
        float v = 0.f;
        if (g < N_NODES) v = x[(size_t)g * D + d] + g_aggr[(size_t)g * D + d];
        __nv_bfloat16 h = __float2bfloat16_rn(v);
        Ah[n * 264 + d] = h;
        Al[n * 264 + d] = __float2bfloat16_rn(v - __bfloat162float(h));
    }
    bg1[tid] = b_g1[tid];
    lng[tid] = ln_g[tid];
    lnb[tid] = ln_b[tid];
    bg2[tid] = b_g2[tid];

    // ---- GEMM1 ----
    float acc1[32][4];
    #pragma unroll
    for (int n = 0; n < 32; n++)
        #pragma unroll
        for (int j = 0; j < 4; j++) acc1[n][j] = 0.f;

    #pragma unroll 1
    for (int kc = 0; kc < 8; kc++) {
        cp_wait0();
        __syncthreads();
        if (kc < 7) prefetch_B(g_Wg1_h, g_Wg1_l, D, (kc + 1) * 32, bbase + ((kc + 1) & 1) * 40960, tid);
        else        prefetch_B(g_Wg2_h, g_Wg2_l, D, 0, bbase, tid);   // chain into GEMM2
        const __nv_bfloat16* Bh = (const __nv_bfloat16*)(smem + N_B + (kc & 1) * 40960);
        const __nv_bfloat16* Bl = Bh + 256 * 40;
        #pragma unroll
        for (int ks = 0; ks < 2; ks++) {
            uint32_t arow = warp * 16 + (lane & 15);
            uint32_t acol = kc * 32 + ks * 16 + ((lane >> 4) << 3);
            uint32_t ah[4], al[4];
            ldsm4(ah, ah_u + (arow * 264 + acol) * 2);
            ldsm4(al, al_u + (arow * 264 + acol) * 2);
            mma_rows<32>(acc1, ah, al, Bh, Bl, 0, ks * 16 + (lane & 3) * 2, lane);
        }
    }

    // ---- bias + in-register LayerNorm + relu + split ----
    float s0 = 0.f, q0 = 0.f, s1 = 0.f, q1 = 0.f;
    #pragma unroll
    for (int ni = 0; ni < 32; ni++) {
        int col = ni * 8 + 2 * (lane & 3);
        float2 b = *(const float2*)&bg1[col];
        acc1[ni][0] += b.x; acc1[ni][1] += b.y;
        acc1[ni][2] += b.x; acc1[ni][3] += b.y;
        s0 += acc1[ni][0] + acc1[ni][1];
        q0 += acc1[ni][0] * acc1[ni][0] + acc1[ni][1] * acc1[ni][1];
        s1 += acc1[ni][2] + acc1[ni][3];
        q1 += acc1[ni][2] * acc1[ni][2] + acc1[ni][3] * acc1[ni][3];
    }
    #pragma unroll
    for (int off = 1; off <= 2; off <<= 1) {
        s0 += __shfl_xor_sync(0xffffffffu, s0, off);
        q0 += __shfl_xor_sync(0xffffffffu, q0, off);
        s1 += __shfl_xor_sync(0xffffffffu, s1, off);
        q1 += __shfl_xor_sync(0xffffffffu, q1, off);
    }
    float mu0 = s0 * (1.f / D), var0 = q0 * (1.f / D) - mu0 * mu0;
    float mu1 = s1 * (1.f / D), var1 = q1 * (1.f / D) - mu1 * mu1;
    float rs0 = rsqrtf(var0 + LN_EPS), rs1 = rsqrtf(var1 + LN_EPS);

    uint32_t fh[64], fl[64];
    #pragma unroll
    for (int ni = 0; ni < 32; ni++) {
        int col = ni * 8 + 2 * (lane & 3);
        float2 g = *(const float2*)&lng[col];
        float2 bb = *(const float2*)&lnb[col];
        float v0 = fmaxf((acc1[ni][0] - mu0) * rs0 * g.x + bb.x, 0.f);
        float v1 = fmaxf((acc1[ni][1] - mu0) * rs0 * g.y + bb.y, 0.f);
        float v2 = fmaxf((acc1[ni][2] - mu1) * rs1 * g.x + bb.x, 0.f);
        float v3 = fmaxf((acc1[ni][3] - mu1) * rs1 * g.y + bb.y, 0.f);
        splitpack(v0, v1, fh[2 * ni],     fl[2 * ni]);
        splitpack(v2, v3, fh[2 * ni + 1], fl[2 * ni + 1]);
    }

    const int R0 = warp * 16 + (lane >> 2);
    const int R1 = R0 + 8;
    const int gr0 = n0 + R0, gr1 = n0 + R1;

    // ---- GEMM2 in two n-halves, continuous prefetch chain ----
    #pragma unroll 1
    for (int half = 0; half < 2; half++) {
        float acc2[16][4];
        #pragma unroll
        for (int n = 0; n < 16; n++)
            #pragma unroll
            for (int j = 0; j < 4; j++) acc2[n][j] = 0.f;

        #pragma unroll
        for (int kc = 0; kc < 8; kc++) {
            int s = half * 8 + kc;
            cp_wait0();
            __syncthreads();
            if (s < 15)
                prefetch_B(g_Wg2_h, g_Wg2_l, D, ((s + 1) & 7) * 32, bbase + ((s + 1) & 1) * 40960, tid);
            const __nv_bfloat16* Bh = (const __nv_bfloat16*)(smem + N_B + (s & 1) * 40960);
            const __nv_bfloat16* Bl = Bh + 256 * 40;
            #pragma unroll
            for (int ks = 0; ks < 2; ks++) {
                int j = kc * 2 + ks;
                mma_rows<16>(acc2, &fh[4 * j], &fl[4 * j], Bh, Bl, half * 16,
                             ks * 16 + (lane & 3) * 2, lane);
            }
        }

        // epilogue: + b_g2 -> out
        #pragma unroll
        for (int ni = 0; ni < 16; ni++) {
            int col = half * 128 + ni * 8 + 2 * (lane & 3);
            float2 b = *(const float2*)&bg2[col];
            if (gr0 < N_NODES)
                *(float2*)&out[(size_t)gr0 * D + col] =
                    make_float2(acc2[ni][0] + b.x, acc2[ni][1] + b.y);
            if (gr1 < N_NODES)
                *(float2*)&out[(size_t)gr1 * D + col] =
                    make_float2(acc2[ni][2] + b.x, acc2[ni][3] + b.y);
        }
    }
}

// ---------------- launch ----------------
extern "C" void kernel_launch(void* const* d_in, const int* in_sizes, int n_in,
                              void* d_out, int out_size)
{
    const float* x         = (const float*)d_in[0];
    const void*  eidx      = d_in[1];
    const float* edge_attr = (const float*)d_in[2];
    const float* W_e1      = (const float*)d_in[3];
    const float* b_e1      = (const float*)d_in[4];
    const float* W_e2      = (const float*)d_in[5];
    const float* b_e2      = (const float*)d_in[6];
    const float* W_le      = (const float*)d_in[7];
    const float* b_le      = (const float*)d_in[8];
    const float* W_g1      = (const float*)d_in[9];
    const float* b_g1      = (const float*)d_in[10];
    const float* ln_g      = (const float*)d_in[11];
    const float* ln_b      = (const float*)d_in[12];
    const float* W_g2      = (const float*)d_in[13];
    const float* b_g2      = (const float*)d_in[14];
    float*       out       = (float*)d_out;

    cudaFuncSetAttribute(edge_kernel, cudaFuncAttributeMaxDynamicSharedMemorySize, EDGE_SMEM_BYTES);
    cudaFuncSetAttribute(node_kernel, cudaFuncAttributeMaxDynamicSharedMemorySize, NODE_SMEM_BYTES);

    detect_idx_kernel<<<1, 256>>>((const int*)eidx);
    convert_idx_kernel<<<(N_EDGES + 255) / 256, 256>>>(eidx);

    prep_Wc<<<64, 256>>>(W_le, W_e2);
    prep_bc<<<256, 256>>>(W_le, b_e2);
    split_weights<<<(D * F + 3 * D * D + 255) / 256, 256>>>(W_e1, W_g1, W_g2);
    zero_aggr<<<(N_NODES * D / 4 + 255) / 256, 256>>>();

    edge_kernel<<<N_EDGES / TE, 256, EDGE_SMEM_BYTES>>>(x, edge_attr, b_e1, b_le);
    node_kernel<<<(N_NODES + TN - 1) / TN, 256, NODE_SMEM_BYTES>>>(x, b_g1, ln_g, ln_b, b_g2, out);
}

// round 8
// speedup vs baseline: 4.0262x; 1.1447x over previous
#include <cuda_runtime.h>
#include <cuda_bf16.h>
#include <stdint.h>

#define N_NODES 50000
#define N_EDGES 800000
#define D 256
#define F 64
#define LN_EPS 1e-5f
#define TE 128
#define TN 128

// ---------------- device scratch ----------------
__device__ float g_Wc[D * D];            // fp32 (W_le @ W_e2), [n][k]
__device__ float g_bc[D];                // W_le @ b_e2
// fragment-packed weights: [k16-slice][ntile(32)][lane(32)] = {bh0,bh1,bl0,bl1}
__device__ uint4 g_We1_f[4 * 1024];      // K=64  -> 4 slices
__device__ uint4 g_Wc_f[16 * 1024];      // K=256 -> 16 slices
__device__ uint4 g_Wg1_f[16 * 1024];
__device__ uint4 g_Wg2_f[16 * 1024];
__device__ __align__(16) float g_aggr[(size_t)N_NODES * D];
__device__ int g_idx_is64;
__device__ int g_srcs[N_EDGES], g_dsts[N_EDGES];

// ---------------- low-level helpers ----------------
__device__ __forceinline__ void red_add_v4(float* p, float4 v) {
    asm volatile("red.global.add.v4.f32 [%0], {%1,%2,%3,%4};"
                 :: "l"(p), "f"(v.x), "f"(v.y), "f"(v.z), "f"(v.w) : "memory");
}
__device__ __forceinline__ uint32_t smem_u32(const void* p) {
    return (uint32_t)__cvta_generic_to_shared(p);
}
__device__ __forceinline__ void cpasync16(uint32_t dst, const void* src) {
    asm volatile("cp.async.cg.shared.global [%0], [%1], 16;" :: "r"(dst), "l"(src));
}
__device__ __forceinline__ void cp_commit() { asm volatile("cp.async.commit_group;"); }
__device__ __forceinline__ void cp_wait0()  { asm volatile("cp.async.wait_group 0;"); }

__device__ __forceinline__ void ldsm4(uint32_t* r, uint32_t addr) {
    asm volatile("ldmatrix.sync.aligned.m8n8.x4.shared.b16 {%0,%1,%2,%3}, [%4];"
                 : "=r"(r[0]), "=r"(r[1]), "=r"(r[2]), "=r"(r[3]) : "r"(addr));
}
__device__ __forceinline__ void mma_bf16(float* c,
    uint32_t a0, uint32_t a1, uint32_t a2, uint32_t a3, uint32_t b0, uint32_t b1) {
    asm volatile("mma.sync.aligned.m16n8k16.row.col.f32.bf16.bf16.f32 "
                 "{%0,%1,%2,%3}, {%4,%5,%6,%7}, {%8,%9}, {%0,%1,%2,%3};"
                 : "+f"(c[0]), "+f"(c[1]), "+f"(c[2]), "+f"(c[3])
                 : "r"(a0), "r"(a1), "r"(a2), "r"(a3), "r"(b0), "r"(b1));
}
__device__ __forceinline__ void splitpack(float a, float b, uint32_t& hi, uint32_t& lo) {
    __nv_bfloat16 ha = __float2bfloat16_rn(a), hb = __float2bfloat16_rn(b);
    __nv_bfloat16 la = __float2bfloat16_rn(a - __bfloat162float(ha));
    __nv_bfloat16 lb = __float2bfloat16_rn(b - __bfloat162float(hb));
    hi = (uint32_t)__bfloat16_as_ushort(ha) | ((uint32_t)__bfloat16_as_ushort(hb) << 16);
    lo = (uint32_t)__bfloat16_as_ushort(la) | ((uint32_t)__bfloat16_as_ushort(lb) << 16);
}

// contiguous 32KB chunk (2 k16-slices) of fragment-packed B -> smem
__device__ __forceinline__ void prefetch_chunk(const uint4* __restrict__ gsrc,
                                               uint32_t b_base, int tid) {
    #pragma unroll
    for (int t = 0; t < 8; t++) {
        int i = tid + t * 256;
        cpasync16(b_base + (uint32_t)i * 16, gsrc + i);
    }
    cp_commit();
}

// one 32-k chunk: warp tile 64x64, A from smem (stride 264 bf16), B fragment-packed
__device__ __forceinline__ void gemm_chunk2(float acc[4][8][4],
    uint32_t ah_u, uint32_t al_u, const uint4* __restrict__ B,
    int k0base, int mg, int ng, int lane)
{
    #pragma unroll
    for (int s = 0; s < 2; s++) {
        uint32_t ahi[4][4], alo[4][4];
        int col = k0base + s * 16 + ((lane >> 4) << 3);
        #pragma unroll
        for (int mt = 0; mt < 4; mt++) {
            int row = mg * 64 + mt * 16 + (lane & 15);
            ldsm4(ahi[mt], ah_u + (uint32_t)(row * 264 + col) * 2);
            ldsm4(alo[mt], al_u + (uint32_t)(row * 264 + col) * 2);
        }
        #pragma unroll
        for (int ni = 0; ni < 8; ni++) {
            uint4 f = B[(s * 32 + ng * 8 + ni) * 32 + lane];
            #pragma unroll
            for (int mt = 0; mt < 4; mt++) {
                mma_bf16(acc[mt][ni], ahi[mt][0], ahi[mt][1], ahi[mt][2], ahi[mt][3], f.x, f.y);
                mma_bf16(acc[mt][ni], ahi[mt][0], ahi[mt][1], ahi[mt][2], ahi[mt][3], f.z, f.w);
                mma_bf16(acc[mt][ni], alo[mt][0], alo[mt][1], alo[mt][2], alo[mt][3], f.x, f.y);
            }
        }
    }
}

// ---------------- index handling (proven) ----------------
__global__ void detect_idx_kernel(const int* __restrict__ p) {
    __shared__ int acc[256];
    int t = threadIdx.x;
    int v = 0;
    #pragma unroll
    for (int i = 0; i < 4; i++) v |= p[(t * 4 + i) * 2 + 1];
    acc[t] = v;
    __syncthreads();
    for (int s = 128; s; s >>= 1) { if (t < s) acc[t] |= acc[t + s]; __syncthreads(); }
    if (t == 0) g_idx_is64 = (acc[0] == 0) ? 1 : 0;
}
__global__ void convert_idx_kernel(const void* __restrict__ eidx) {
    int i = blockIdx.x * blockDim.x + threadIdx.x;
    if (i >= N_EDGES) return;
    int s, d;
    if (g_idx_is64) {
        const long long* p = (const long long*)eidx;
        s = (int)p[i]; d = (int)p[(size_t)N_EDGES + i];
    } else {
        const int* p = (const int*)eidx;
        s = p[i]; d = p[N_EDGES + i];
    }
    g_srcs[i] = min(max(s, 0), N_NODES - 1);
    g_dsts[i] = min(max(d, 0), N_NODES - 1);
}

// ---------------- prep kernels ----------------
__global__ void prep_Wc(const float* __restrict__ W_le, const float* __restrict__ W_e2) {
    __shared__ float wle[4][256];
    int b = blockIdx.x, t = threadIdx.x;       // 64 blocks
    #pragma unroll
    for (int r = 0; r < 4; r++) wle[r][t] = W_le[(b * 4 + r) * 256 + t];
    __syncthreads();
    float a0 = 0, a1 = 0, a2 = 0, a3 = 0;
    #pragma unroll 4
    for (int j = 0; j < 256; j++) {
        float w = W_e2[j * 256 + t];
        a0 += wle[0][j] * w; a1 += wle[1][j] * w;
        a2 += wle[2][j] * w; a3 += wle[3][j] * w;
    }
    g_Wc[(b * 4 + 0) * 256 + t] = a0;
    g_Wc[(b * 4 + 1) * 256 + t] = a1;
    g_Wc[(b * 4 + 2) * 256 + t] = a2;
    g_Wc[(b * 4 + 3) * 256 + t] = a3;
}
__global__ void prep_bc(const float* __restrict__ W_le, const float* __restrict__ b_e2) {
    __shared__ float red[256];
    int d = blockIdx.x, t = threadIdx.x;       // 256 blocks
    red[t] = W_le[d * 256 + t] * b_e2[t];
    __syncthreads();
    for (int s = 128; s; s >>= 1) { if (t < s) red[t] += red[t + s]; __syncthreads(); }
    if (t == 0) g_bc[d] = red[0];
}
// pack all weights into mma-fragment order
__global__ void pack_frags(const float* __restrict__ We1,
                           const float* __restrict__ Wg1,
                           const float* __restrict__ Wg2) {
    int id = blockIdx.x * 256 + threadIdx.x;     // 53248 total
    const float* W; uint4* dst; int K, rel;
    if (id < 4096)       { W = We1;  dst = g_We1_f; K = 64;  rel = id; }
    else if (id < 20480) { W = g_Wc; dst = g_Wc_f;  K = 256; rel = id - 4096; }
    else if (id < 36864) { W = Wg1;  dst = g_Wg1_f; K = 256; rel = id - 20480; }
    else                 { W = Wg2;  dst = g_Wg2_f; K = 256; rel = id - 36864; }
    int slice = rel >> 10, idx = rel & 1023, nt = idx >> 5, lane = idx & 31;
    int nr = lane >> 2, kq = lane & 3;
    int n = nt * 8 + nr, k0 = slice * 16 + kq * 2;
    float w00 = W[n * K + k0],     w01 = W[n * K + k0 + 1];
    float w08 = W[n * K + k0 + 8], w09 = W[n * K + k0 + 9];
    uint32_t bh0, bl0, bh1, bl1;
    splitpack(w00, w01, bh0, bl0);
    splitpack(w08, w09, bh1, bl1);
    dst[rel] = make_uint4(bh0, bh1, bl0, bl1);
}
__global__ void zero_aggr() {
    size_t i = (size_t)blockIdx.x * blockDim.x + threadIdx.x;
    if (i < (size_t)N_NODES * D / 4)
        ((float4*)g_aggr)[i] = make_float4(0.f, 0.f, 0.f, 0.f);
}

// ---------------- edge kernel ----------------
#define E_AH   0           // bf16 [128][264] = 67584
#define E_AL   67584
#define E_B    135168      // 2 x 32768
#define E_SML  200704      // pol 512 | srcs 512 | dsts 512 | bcs 1024 | bls 1024 | be1s 1024
#define EDGE_SMEM_BYTES 205312
#define EMB_STRIDE 260     // fp32 row stride for emb staging (>=256, 1040B pitch, 16B-aligned)

__global__ __launch_bounds__(256, 1) void edge_kernel(
    const float* __restrict__ x,
    const float* __restrict__ edge_attr,
    const float* __restrict__ b_e1,
    const float* __restrict__ b_le)
{
    extern __shared__ char smem[];
    __nv_bfloat16* Ah = (__nv_bfloat16*)(smem + E_AH);
    __nv_bfloat16* Al = (__nv_bfloat16*)(smem + E_AL);
    uint4* Bbuf = (uint4*)(smem + E_B);
    float* pol  = (float*)(smem + E_SML);
    int*   srcs = (int*)(smem + E_SML + 512);
    int*   dsts = (int*)(smem + E_SML + 1024);
    float* bcs  = (float*)(smem + E_SML + 1536);
    float* bls  = (float*)(smem + E_SML + 2560);
    float* be1s = (float*)(smem + E_SML + 3584);

    const int tid  = threadIdx.x;
    const int lane = tid & 31;
    const int warp = tid >> 5;
    const int mg   = warp >> 2;     // 0..1 (row group of 64)
    const int ng   = warp & 3;      // 0..3 (col group of 64)
    const int nr   = lane >> 2, kq = lane & 3;
    const int e0   = blockIdx.x * TE;
    const uint32_t ah_u = smem_u32(Ah), al_u = smem_u32(Al);
    const uint32_t bbase = smem_u32(smem + E_B);

    prefetch_chunk(g_We1_f, bbase, tid);          // GEMM1 chunk0 -> buf0

    // stage raw split into A cols 0..63
    #pragma unroll
    for (int t = 0; t < 32; t++) {
        int i = tid + t * 256;
        int e = i >> 6, k = i & 63;
        float v = edge_attr[(size_t)(e0 + e) * 65 + 1 + k];
        __nv_bfloat16 h = __float2bfloat16_rn(v);
        Ah[e * 264 + k] = h;
        Al[e * 264 + k] = __float2bfloat16_rn(v - __bfloat162float(h));
    }
    if (tid < TE) {
        float p = edge_attr[(size_t)(e0 + tid) * 65];
        pol[tid] = fminf(fmaxf(p, 0.f), 1.f) + 0.01f;
        srcs[tid] = g_srcs[e0 + tid];
        dsts[tid] = g_dsts[e0 + tid];
    } else {
        int t2 = tid - 128;
        bcs[t2]  = g_bc[t2];  bcs[t2 + 128]  = g_bc[t2 + 128];
        bls[t2]  = b_le[t2];  bls[t2 + 128]  = b_le[t2 + 128];
        be1s[t2] = b_e1[t2];  be1s[t2 + 128] = b_e1[t2 + 128];
    }

    float acc[4][8][4];
    #pragma unroll
    for (int a = 0; a < 4; a++)
        #pragma unroll
        for (int b = 0; b < 8; b++)
            #pragma unroll
            for (int c = 0; c < 4; c++) acc[a][b][c] = 0.f;

    // ---- GEMM1: h1 = raw @ We1^T (K=64, 2 chunks) ----
    #pragma unroll
    for (int kc = 0; kc < 2; kc++) {
        cp_wait0();
        __syncthreads();
        if (kc == 0) prefetch_chunk(g_We1_f + 2048, bbase + 32768, tid);
        else         prefetch_chunk(g_Wc_f, bbase, tid);        // GEMM2 chunk0 -> buf0
        gemm_chunk2(acc, ah_u, al_u, Bbuf + (kc & 1) * 2048, kc * 32, mg, ng, lane);
    }
    __syncthreads();   // all raw reads done before overwrite

    // ---- h1 = relu(acc + b_e1), split, store back into A (cols = GEMM2 k) ----
    #pragma unroll
    for (int mt = 0; mt < 4; mt++) {
        int r0 = mg * 64 + mt * 16 + nr, r1 = r0 + 8;
        #pragma unroll
        for (int ni = 0; ni < 8; ni++) {
            int c = ng * 64 + ni * 8 + kq * 2;
            float2 b = *(const float2*)&be1s[c];
            float v0 = fmaxf(acc[mt][ni][0] + b.x, 0.f);
            float v1 = fmaxf(acc[mt][ni][1] + b.y, 0.f);
            float v2 = fmaxf(acc[mt][ni][2] + b.x, 0.f);
            float v3 = fmaxf(acc[mt][ni][3] + b.y, 0.f);
            uint32_t hi, lo;
            splitpack(v0, v1, hi, lo);
            *(uint32_t*)&Ah[r0 * 264 + c] = hi;
            *(uint32_t*)&Al[r0 * 264 + c] = lo;
            splitpack(v2, v3, hi, lo);
            *(uint32_t*)&Ah[r1 * 264 + c] = hi;
            *(uint32_t*)&Al[r1 * 264 + c] = lo;
            acc[mt][ni][0] = acc[mt][ni][1] = acc[mt][ni][2] = acc[mt][ni][3] = 0.f;
        }
    }

    // ---- GEMM2: h2 = h1 @ Wc^T (K=256, 8 chunks, single stream) ----
    #pragma unroll 1
    for (int kc = 0; kc < 8; kc++) {
        cp_wait0();
        __syncthreads();
        if (kc < 7)
            prefetch_chunk(g_Wc_f + (kc + 1) * 2048, bbase + ((kc + 1) & 1) * 32768, tid);
        gemm_chunk2(acc, ah_u, al_u, Bbuf + (kc & 1) * 2048, kc * 32, mg, ng, lane);
    }
    __syncthreads();   // A reads done; emb may alias A region

    // ---- epilogue: emb = pol*(h2 + bc) + bl -> smem (aliases A, stride 260) ----
    float* emb = (float*)smem;     // [128][EMB_STRIDE] = 133120 B <= 135168 B
    #pragma unroll
    for (int mt = 0; mt < 4; mt++) {
        int r0 = mg * 64 + mt * 16 + nr, r1 = r0 + 8;
        float p0 = pol[r0], p1 = pol[r1];
        #pragma unroll
        for (int ni = 0; ni < 8; ni++) {
            int c = ng * 64 + ni * 8 + kq * 2;
            float2 bcv = *(const float2*)&bcs[c];
            float2 blv = *(const float2*)&bls[c];
            *(float2*)&emb[r0 * EMB_STRIDE + c] =
                make_float2(p0 * (acc[mt][ni][0] + bcv.x) + blv.x,
                            p0 * (acc[mt][ni][1] + bcv.y) + blv.y);
            *(float2*)&emb[r1 * EMB_STRIDE + c] =
                make_float2(p1 * (acc[mt][ni][2] + bcv.x) + blv.x,
                            p1 * (acc[mt][ni][3] + bcv.y) + blv.y);
        }
    }
    __syncthreads();

    // ---- gather x[src], msg = relu(x+emb), scatter-add ----
    #pragma unroll
    for (int it = 0; it < 16; it++) {
        int r = it * 8 + warp;
        int si = srcs[r], di = dsts[r];
        const float4* xp = (const float4*)(x + (size_t)si * D);
        float* ap = &g_aggr[(size_t)di * D];
        #pragma unroll
        for (int seg = 0; seg < 2; seg++) {
            int c4 = lane + seg * 32;
            float4 ee = *(const float4*)&emb[r * EMB_STRIDE + c4 * 4];
            float4 xv = xp[c4];
            float4 m;
            m.x = fmaxf(xv.x + ee.x, 0.f);
            m.y = fmaxf(xv.y + ee.y, 0.f);
            m.z = fmaxf(xv.z + ee.z, 0.f);
            m.w = fmaxf(xv.w + ee.w, 0.f);
            red_add_v4(ap + c4 * 4, m);
        }
    }
}

// ---------------- node kernel ----------------
#define N_AH   0
#define N_AL   67584
#define N_B    135168
#define N_PS   200704     // float2 ps[128][4]  = 4096
#define N_SML  204800     // bg1 | lng | lnb | bg2 (4 x 1024)
#define NODE_SMEM_BYTES 208896

__global__ __launch_bounds__(256, 1) void node_kernel(
    const float* __restrict__ x,
    const float* __restrict__ b_g1,
    const float* __restrict__ ln_g,
    const float* __restrict__ ln_b,
    const float* __restrict__ b_g2,
    float* __restrict__ out)
{
    extern __shared__ char smem[];
    __nv_bfloat16* Ah = (__nv_bfloat16*)(smem + N_AH);
    __nv_bfloat16* Al = (__nv_bfloat16*)(smem + N_AL);
    uint4* Bbuf = (uint4*)(smem + N_B);
    float2* ps  = (float2*)(smem + N_PS);    // [128 rows][4 ngroups]
    float* bg1 = (float*)(smem + N_SML);
    float* lng = (float*)(smem + N_SML + 1024);
    float* lnb = (float*)(smem + N_SML + 2048);
    float* bg2 = (float*)(smem + N_SML + 3072);

    const int tid  = threadIdx.x;
    const int lane = tid & 31;
    const int warp = tid >> 5;
    const int mg   = warp >> 2;
    const int ng   = warp & 3;
    const int nr   = lane >> 2, kq = lane & 3;
    const int n0   = blockIdx.x * TN;
    const uint32_t ah_u = smem_u32(Ah), al_u = smem_u32(Al);
    const uint32_t bbase = smem_u32(smem + N_B);

    prefetch_chunk(g_Wg1_f, bbase, tid);

    // stage xin = x + aggr, split
    for (int i = tid; i < TN * D; i += 256) {
        int n = i >> 8, d = i & 255;
        int g = n0 + n;
        float v = 0.f;
        if (g < N_NODES) v = x[(size_t)g * D + d] + g_aggr[(size_t)g * D + d];
        __nv_bfloat16 h = __float2bfloat16_rn(v);
        Ah[n * 264 + d] = h;
        Al[n * 264 + d] = __float2bfloat16_rn(v - __bfloat162float(h));
    }
    bg1[tid] = b_g1[tid];
    lng[tid] = ln_g[tid];
    lnb[tid] = ln_b[tid];
    bg2[tid] = b_g2[tid];

    float acc[4][8][4];
    #pragma unroll
    for (int a = 0; a < 4; a++)
        #pragma unroll
        for (int b = 0; b < 8; b++)
            #pragma unroll
            for (int c = 0; c < 4; c++) acc[a][b][c] = 0.f;

    // ---- GEMM1 ----
    #pragma unroll 1
    for (int kc = 0; kc < 8; kc++) {
        cp_wait0();
        __syncthreads();
        if (kc < 7) prefetch_chunk(g_Wg1_f + (kc + 1) * 2048, bbase + ((kc + 1) & 1) * 32768, tid);
        else        prefetch_chunk(g_Wg2_f, bbase, tid);       // chain into GEMM2
        gemm_chunk2(acc, ah_u, al_u, Bbuf + (kc & 1) * 2048, kc * 32, mg, ng, lane);
    }

    // ---- bias + partial LN stats (per-warp 64-col partials) ----
    #pragma unroll
    for (int mt = 0; mt < 4; mt++) {
        float sl = 0.f, ql = 0.f, sh = 0.f, qh = 0.f;
        #pragma unroll
        for (int ni = 0; ni < 8; ni++) {
            int c = ng * 64 + ni * 8 + kq * 2;
            float2 b = *(const float2*)&bg1[c];
            float v0 = acc[mt][ni][0] + b.x, v1 = acc[mt][ni][1] + b.y;
            float v2 = acc[mt][ni][2] + b.x, v3 = acc[mt][ni][3] + b.y;
            acc[mt][ni][0] = v0; acc[mt][ni][1] = v1;
            acc[mt][ni][2] = v2; acc[mt][ni][3] = v3;
            sl += v0 + v1; ql += v0 * v0 + v1 * v1;
            sh += v2 + v3; qh += v2 * v2 + v3 * v3;
        }
        #pragma unroll
        for (int off = 1; off <= 2; off <<= 1) {
            sl += __shfl_xor_sync(0xffffffffu, sl, off);
            ql += __shfl_xor_sync(0xffffffffu, ql, off);
            sh += __shfl_xor_sync(0xffffffffu, sh, off);
            qh += __shfl_xor_sync(0xffffffffu, qh, off);
        }
        if (kq == 0) {
            int r0 = mg * 64 + mt * 16 + nr;
            ps[r0 * 4 + ng]       = make_float2(sl, ql);
            ps[(r0 + 8) * 4 + ng] = make_float2(sh, qh);
        }
    }
    __syncthreads();

    // full stats per row, normalize + relu + split -> A (overwrites xin)
    float mu[4][2], rs[4][2];
    #pragma unroll
    for (int mt = 0; mt < 4; mt++) {
        int r0 = mg * 64 + mt * 16 + nr;
        #pragma unroll
        for (int h = 0; h < 2; h++) {
            float s = 0.f, q = 0.f;
            #pragma unroll
            for (int g = 0; g < 4; g++) {
                float2 p = ps[(r0 + h * 8) * 4 + g];
                s += p.x; q += p.y;
            }
            float m = s * (1.f / D);
            float v = q * (1.f / D) - m * m;
            mu[mt][h] = m;
            rs[mt][h] = rsqrtf(v + LN_EPS);
        }
    }
    #pragma unroll
    for (int mt = 0; mt < 4; mt++) {
        int r0 = mg * 64 + mt * 16 + nr, r1 = r0 + 8;
        #pragma unroll
        for (int ni = 0; ni < 8; ni++) {
            int c = ng * 64 + ni * 8 + kq * 2;
            float2 g = *(const float2*)&lng[c];
            float2 bb = *(const float2*)&lnb[c];
            float v0 = fmaxf((acc[mt][ni][0] - mu[mt][0]) * rs[mt][0] * g.x + bb.x, 0.f);
            float v1 = fmaxf((acc[mt][ni][1] - mu[mt][0]) * rs[mt][0] * g.y + bb.y, 0.f);
            float v2 = fmaxf((acc[mt][ni][2] - mu[mt][1]) * rs[mt][1] * g.x + bb.x, 0.f);
            float v3 = fmaxf((acc[mt][ni][3] - mu[mt][1]) * rs[mt][1] * g.y + bb.y, 0.f);
            uint32_t hi, lo;
            splitpack(v0, v1, hi, lo);
            *(uint32_t*)&Ah[r0 * 264 + c] = hi;
            *(uint32_t*)&Al[r0 * 264 + c] = lo;
            splitpack(v2, v3, hi, lo);
            *(uint32_t*)&Ah[r1 * 264 + c] = hi;
            *(uint32_t*)&Al[r1 * 264 + c] = lo;
            acc[mt][ni][0] = acc[mt][ni][1] = acc[mt][ni][2] = acc[mt][ni][3] = 0.f;
        }
    }

    // ---- GEMM2 (first sync inside loop orders the A stores above) ----
    #pragma unroll 1
    for (int kc = 0; kc < 8; kc++) {
        cp_wait0();
        __syncthreads();
        if (kc < 7) prefetch_chunk(g_Wg2_f + (kc + 1) * 2048, bbase + ((kc + 1) & 1) * 32768, tid);
        gemm_chunk2(acc, ah_u, al_u, Bbuf + (kc & 1) * 2048, kc * 32, mg, ng, lane);
    }

    // ---- epilogue: + b_g2 -> out ----
    #pragma unroll
    for (int mt = 0; mt < 4; mt++) {
        int r0 = mg * 64 + mt * 16 + nr, r1 = r0 + 8;
        int gr0 = n0 + r0, gr1 = n0 + r1;
        #pragma unroll
        for (int ni = 0; ni < 8; ni++) {
            int c = ng * 64 + ni * 8 + kq * 2;
            float2 b = *(const float2*)&bg2[c];
            if (gr0 < N_NODES)
                *(float2*)&out[(size_t)gr0 * D + c] =
                    make_float2(acc[mt][ni][0] + b.x, acc[mt][ni][1] + b.y);
            if (gr1 < N_NODES)
                *(float2*)&out[(size_t)gr1 * D + c] =
                    make_float2(acc[mt][ni][2] + b.x, acc[mt][ni][3] + b.y);
        }
    }
}

// ---------------- launch ----------------
extern "C" void kernel_launch(void* const* d_in, const int* in_sizes, int n_in,
                              void* d_out, int out_size)
{
    const float* x         = (const float*)d_in[0];
    const void*  eidx      = d_in[1];
    const float* edge_attr = (const float*)d_in[2];
    const float* W_e1      = (const float*)d_in[3];
    const float* b_e1      = (const float*)d_in[4];
    const float* W_e2      = (const float*)d_in[5];
    const float* b_e2      = (const float*)d_in[6];
    const float* W_le      = (const float*)d_in[7];
    const float* b_le      = (const float*)d_in[8];
    const float* W_g1      = (const float*)d_in[9];
    const float* b_g1      = (const float*)d_in[10];
    const float* ln_g      = (const float*)d_in[11];
    const float* ln_b      = (const float*)d_in[12];
    const float* W_g2      = (const float*)d_in[13];
    const float* b_g2      = (const float*)d_in[14];
    float*       out       = (float*)d_out;

    cudaFuncSetAttribute(edge_kernel, cudaFuncAttributeMaxDynamicSharedMemorySize, EDGE_SMEM_BYTES);
    cudaFuncSetAttribute(node_kernel, cudaFuncAttributeMaxDynamicSharedMemorySize, NODE_SMEM_BYTES);

    detect_idx_kernel<<<1, 256>>>((const int*)eidx);
    convert_idx_kernel<<<(N_EDGES + 255) / 256, 256>>>(eidx);

    prep_Wc<<<64, 256>>>(W_le, W_e2);
    prep_bc<<<256, 256>>>(W_le, b_e2);
    pack_frags<<<208, 256>>>(W_e1, W_g1, W_g2);
    zero_aggr<<<(N_NODES * D / 4 + 255) / 256, 256>>>();

    edge_kernel<<<N_EDGES / TE, 256, EDGE_SMEM_BYTES>>>(x, edge_attr, b_e1, b_le);
    node_kernel<<<(N_NODES + TN - 1) / TN, 256, NODE_SMEM_BYTES>>>(x, b_g1, ln_g, ln_b, b_g2, out);
}

// round 9
// speedup vs baseline: 5.2183x; 1.2961x over previous
#include <cuda_runtime.h>
#include <cuda_bf16.h>
#include <cuda_fp16.h>
#include <stdint.h>

#define N_NODES 50000
#define N_EDGES 800000
#define D 256
#define F 64
#define LN_EPS 1e-5f
#define TE 128
#define TN 128

// ---------------- device scratch ----------------
__device__ float g_Wc[D * D];            // fp32 (W_le @ W_e2), [n][k]
__device__ float g_bc[D];                // W_le @ b_e2
// fragment-packed fp16 weights (hi only): [k16-slice][ntile(32)][lane(32)] = {h0,h1}
__device__ uint2 g_We1_f[4 * 1024];      // K=64  -> 4 slices
__device__ uint2 g_Wc_f[16 * 1024];      // K=256 -> 16 slices
__device__ uint2 g_Wg1_f[16 * 1024];
__device__ uint2 g_Wg2_f[16 * 1024];
__device__ __align__(16) float g_aggr[(size_t)N_NODES * D];
__device__ int g_idx_is64;
__device__ int g_srcs[N_EDGES], g_dsts[N_EDGES];

// ---------------- low-level helpers ----------------
__device__ __forceinline__ void red_add_v4(float* p, float4 v) {
    asm volatile("red.global.add.v4.f32 [%0], {%1,%2,%3,%4};"
                 :: "l"(p), "f"(v.x), "f"(v.y), "f"(v.z), "f"(v.w) : "memory");
}
__device__ __forceinline__ uint32_t smem_u32(const void* p) {
    return (uint32_t)__cvta_generic_to_shared(p);
}
__device__ __forceinline__ void cpasync16(uint32_t dst, const void* src) {
    asm volatile("cp.async.cg.shared.global [%0], [%1], 16;" :: "r"(dst), "l"(src));
}
__device__ __forceinline__ void cp_commit() { asm volatile("cp.async.commit_group;"); }
__device__ __forceinline__ void cp_wait0()  { asm volatile("cp.async.wait_group 0;"); }

__device__ __forceinline__ void ldsm4(uint32_t* r, uint32_t addr) {
    asm volatile("ldmatrix.sync.aligned.m8n8.x4.shared.b16 {%0,%1,%2,%3}, [%4];"
                 : "=r"(r[0]), "=r"(r[1]), "=r"(r[2]), "=r"(r[3]) : "r"(addr));
}
__device__ __forceinline__ void mma_f16(float* c,
    uint32_t a0, uint32_t a1, uint32_t a2, uint32_t a3, uint32_t b0, uint32_t b1) {
    asm volatile("mma.sync.aligned.m16n8k16.row.col.f32.f16.f16.f32 "
                 "{%0,%1,%2,%3}, {%4,%5,%6,%7}, {%8,%9}, {%0,%1,%2,%3};"
                 : "+f"(c[0]), "+f"(c[1]), "+f"(c[2]), "+f"(c[3])
                 : "r"(a0), "r"(a1), "r"(a2), "r"(a3), "r"(b0), "r"(b1));
}
// fp16 hi/lo split of two fp32 values, packed
__device__ __forceinline__ void splitpack(float a, float b, uint32_t& hi, uint32_t& lo) {
    __half ha = __float2half_rn(a), hb = __float2half_rn(b);
    __half la = __float2half_rn(a - __half2float(ha));
    __half lb = __float2half_rn(b - __half2float(hb));
    hi = (uint32_t)__half_as_ushort(ha) | ((uint32_t)__half_as_ushort(hb) << 16);
    lo = (uint32_t)__half_as_ushort(la) | ((uint32_t)__half_as_ushort(lb) << 16);
}
__device__ __forceinline__ uint32_t pack_f16hi(float a, float b) {
    return (uint32_t)__half_as_ushort(__float2half_rn(a)) |
           ((uint32_t)__half_as_ushort(__float2half_rn(b)) << 16);
}

// contiguous 16KB chunk (2 k16-slices, hi-only) of fragment-packed B -> smem
__device__ __forceinline__ void prefetch_chunk(const uint2* __restrict__ gsrc,
                                               uint32_t b_base, int tid) {
    const uint4* g4 = (const uint4*)gsrc;
    #pragma unroll
    for (int t = 0; t < 4; t++) {
        int i = tid + t * 256;          // 1024 x 16B = 16 KB
        cpasync16(b_base + (uint32_t)i * 16, g4 + i);
    }
    cp_commit();
}

// one 32-k chunk: warp tile 64x64, A hi/lo fp16 from smem (stride 264), B hi-only
__device__ __forceinline__ void gemm_chunk2(float acc[4][8][4],
    uint32_t ah_u, uint32_t al_u, const uint2* __restrict__ B,
    int k0base, int mg, int ng, int lane)
{
    #pragma unroll
    for (int s = 0; s < 2; s++) {
        uint32_t ahi[4][4], alo[4][4];
        int col = k0base + s * 16 + ((lane >> 4) << 3);
        #pragma unroll
        for (int mt = 0; mt < 4; mt++) {
            int row = mg * 64 + mt * 16 + (lane & 15);
            ldsm4(ahi[mt], ah_u + (uint32_t)(row * 264 + col) * 2);
            ldsm4(alo[mt], al_u + (uint32_t)(row * 264 + col) * 2);
        }
        #pragma unroll
        for (int ni = 0; ni < 8; ni++) {
            uint2 f = B[(s * 32 + ng * 8 + ni) * 32 + lane];
            #pragma unroll
            for (int mt = 0; mt < 4; mt++) {
                mma_f16(acc[mt][ni], ahi[mt][0], ahi[mt][1], ahi[mt][2], ahi[mt][3], f.x, f.y);
                mma_f16(acc[mt][ni], alo[mt][0], alo[mt][1], alo[mt][2], alo[mt][3], f.x, f.y);
            }
        }
    }
}

// ---------------- index handling (proven) ----------------
__global__ void detect_idx_kernel(const int* __restrict__ p) {
    __shared__ int acc[256];
    int t = threadIdx.x;
    int v = 0;
    #pragma unroll
    for (int i = 0; i < 4; i++) v |= p[(t * 4 + i) * 2 + 1];
    acc[t] = v;
    __syncthreads();
    for (int s = 128; s; s >>= 1) { if (t < s) acc[t] |= acc[t + s]; __syncthreads(); }
    if (t == 0) g_idx_is64 = (acc[0] == 0) ? 1 : 0;
}
__global__ void convert_idx_kernel(const void* __restrict__ eidx) {
    int i = blockIdx.x * blockDim.x + threadIdx.x;
    if (i >= N_EDGES) return;
    int s, d;
    if (g_idx_is64) {
        const long long* p = (const long long*)eidx;
        s = (int)p[i]; d = (int)p[(size_t)N_EDGES + i];
    } else {
        const int* p = (const int*)eidx;
        s = p[i]; d = p[N_EDGES + i];
    }
    g_srcs[i] = min(max(s, 0), N_NODES - 1);
    g_dsts[i] = min(max(d, 0), N_NODES - 1);
}

// ---------------- prep kernels ----------------
__global__ void prep_Wc(const float* __restrict__ W_le, const float* __restrict__ W_e2) {
    __shared__ float wle[4][256];
    int b = blockIdx.x, t = threadIdx.x;       // 64 blocks
    #pragma unroll
    for (int r = 0; r < 4; r++) wle[r][t] = W_le[(b * 4 + r) * 256 + t];
    __syncthreads();
    float a0 = 0, a1 = 0, a2 = 0, a3 = 0;
    #pragma unroll 4
    for (int j = 0; j < 256; j++) {
        float w = W_e2[j * 256 + t];
        a0 += wle[0][j] * w; a1 += wle[1][j] * w;
        a2 += wle[2][j] * w; a3 += wle[3][j] * w;
    }
    g_Wc[(b * 4 + 0) * 256 + t] = a0;
    g_Wc[(b * 4 + 1) * 256 + t] = a1;
    g_Wc[(b * 4 + 2) * 256 + t] = a2;
    g_Wc[(b * 4 + 3) * 256 + t] = a3;
}
__global__ void prep_bc(const float* __restrict__ W_le, const float* __restrict__ b_e2) {
    __shared__ float red[256];
    int d = blockIdx.x, t = threadIdx.x;       // 256 blocks
    red[t] = W_le[d * 256 + t] * b_e2[t];
    __syncthreads();
    for (int s = 128; s; s >>= 1) { if (t < s) red[t] += red[t + s]; __syncthreads(); }
    if (t == 0) g_bc[d] = red[0];
}
// pack all weights into mma-fragment order (fp16 hi only)
__global__ void pack_frags(const float* __restrict__ We1,
                           const float* __restrict__ Wg1,
                           const float* __restrict__ Wg2) {
    int id = blockIdx.x * 256 + threadIdx.x;     // 53248 total
    const float* W; uint2* dst; int K, rel;
    if (id < 4096)       { W = We1;  dst = g_We1_f; K = 64;  rel = id; }
    else if (id < 20480) { W = g_Wc; dst = g_Wc_f;  K = 256; rel = id - 4096; }
    else if (id < 36864) { W = Wg1;  dst = g_Wg1_f; K = 256; rel = id - 20480; }
    else                 { W = Wg2;  dst = g_Wg2_f; K = 256; rel = id - 36864; }
    int slice = rel >> 10, idx = rel & 1023, nt = idx >> 5, lane = idx & 31;
    int nr = lane >> 2, kq = lane & 3;
    int n = nt * 8 + nr, k0 = slice * 16 + kq * 2;
    uint32_t h0 = pack_f16hi(W[n * K + k0],     W[n * K + k0 + 1]);
    uint32_t h1 = pack_f16hi(W[n * K + k0 + 8], W[n * K + k0 + 9]);
    dst[rel] = make_uint2(h0, h1);
}
__global__ void zero_aggr() {
    size_t i = (size_t)blockIdx.x * blockDim.x + threadIdx.x;
    if (i < (size_t)N_NODES * D / 4)
        ((float4*)g_aggr)[i] = make_float4(0.f, 0.f, 0.f, 0.f);
}

// ---------------- edge kernel ----------------
#define E_AH   0           // fp16 [128][264] = 67584
#define E_AL   67584
#define E_B    135168      // 2 x 16384
#define E_SML  167936      // pol 512 | srcs 512 | dsts 512 | bcs 1024 | bls 1024 | be1s 1024
#define EDGE_SMEM_BYTES 172544
#define EMB_STRIDE 260     // fp32 row stride for emb staging (1040B pitch, 16B-aligned)

__global__ __launch_bounds__(256, 1) void edge_kernel(
    const float* __restrict__ x,
    const float* __restrict__ edge_attr,
    const float* __restrict__ b_e1,
    const float* __restrict__ b_le)
{
    extern __shared__ char smem[];
    __half* Ah = (__half*)(smem + E_AH);
    __half* Al = (__half*)(smem + E_AL);
    uint2* Bbuf = (uint2*)(smem + E_B);
    float* pol  = (float*)(smem + E_SML);
    int*   srcs = (int*)(smem + E_SML + 512);
    int*   dsts = (int*)(smem + E_SML + 1024);
    float* bcs  = (float*)(smem + E_SML + 1536);
    float* bls  = (float*)(smem + E_SML + 2560);
    float* be1s = (float*)(smem + E_SML + 3584);

    const int tid  = threadIdx.x;
    const int lane = tid & 31;
    const int warp = tid >> 5;
    const int mg   = warp >> 2;     // 0..1 (row group of 64)
    const int ng   = warp & 3;      // 0..3 (col group of 64)
    const int nr   = lane >> 2, kq = lane & 3;
    const int e0   = blockIdx.x * TE;
    const uint32_t ah_u = smem_u32(Ah), al_u = smem_u32(Al);
    const uint32_t bbase = smem_u32(smem + E_B);

    prefetch_chunk(g_We1_f, bbase, tid);          // GEMM1 chunk0 -> buf0

    // stage raw split into A cols 0..63
    #pragma unroll
    for (int t = 0; t < 32; t++) {
        int i = tid + t * 256;
        int e = i >> 6, k = i & 63;
        float v = edge_attr[(size_t)(e0 + e) * 65 + 1 + k];
        __half h = __float2half_rn(v);
        Ah[e * 264 + k] = h;
        Al[e * 264 + k] = __float2half_rn(v - __half2float(h));
    }
    if (tid < TE) {
        float p = edge_attr[(size_t)(e0 + tid) * 65];
        pol[tid] = fminf(fmaxf(p, 0.f), 1.f) + 0.01f;
        srcs[tid] = g_srcs[e0 + tid];
        dsts[tid] = g_dsts[e0 + tid];
    } else {
        int t2 = tid - 128;
        bcs[t2]  = g_bc[t2];  bcs[t2 + 128]  = g_bc[t2 + 128];
        bls[t2]  = b_le[t2];  bls[t2 + 128]  = b_le[t2 + 128];
        be1s[t2] = b_e1[t2];  be1s[t2 + 128] = b_e1[t2 + 128];
    }

    float acc[4][8][4];
    #pragma unroll
    for (int a = 0; a < 4; a++)
        #pragma unroll
        for (int b = 0; b < 8; b++)
            #pragma unroll
            for (int c = 0; c < 4; c++) acc[a][b][c] = 0.f;

    // ---- GEMM1: h1 = raw @ We1^T (K=64, 2 chunks) ----
    #pragma unroll
    for (int kc = 0; kc < 2; kc++) {
        cp_wait0();
        __syncthreads();
        if (kc == 0) prefetch_chunk(g_We1_f + 2048, bbase + 16384, tid);
        else         prefetch_chunk(g_Wc_f, bbase, tid);        // GEMM2 chunk0 -> buf0
        gemm_chunk2(acc, ah_u, al_u, Bbuf + (kc & 1) * 2048, kc * 32, mg, ng, lane);
    }
    __syncthreads();   // all raw reads done before overwrite

    // ---- h1 = relu(acc + b_e1), split, store back into A (cols = GEMM2 k) ----
    #pragma unroll
    for (int mt = 0; mt < 4; mt++) {
        int r0 = mg * 64 + mt * 16 + nr, r1 = r0 + 8;
        #pragma unroll
        for (int ni = 0; ni < 8; ni++) {
            int c = ng * 64 + ni * 8 + kq * 2;
            float2 b = *(const float2*)&be1s[c];
            float v0 = fmaxf(acc[mt][ni][0] + b.x, 0.f);
            float v1 = fmaxf(acc[mt][ni][1] + b.y, 0.f);
            float v2 = fmaxf(acc[mt][ni][2] + b.x, 0.f);
            float v3 = fmaxf(acc[mt][ni][3] + b.y, 0.f);
            uint32_t hi, lo;
            splitpack(v0, v1, hi, lo);
            *(uint32_t*)&Ah[r0 * 264 + c] = hi;
            *(uint32_t*)&Al[r0 * 264 + c] = lo;
            splitpack(v2, v3, hi, lo);
            *(uint32_t*)&Ah[r1 * 264 + c] = hi;
            *(uint32_t*)&Al[r1 * 264 + c] = lo;
            acc[mt][ni][0] = acc[mt][ni][1] = acc[mt][ni][2] = acc[mt][ni][3] = 0.f;
        }
    }

    // ---- GEMM2: h2 = h1 @ Wc^T (K=256, 8 chunks, single stream) ----
    #pragma unroll 1
    for (int kc = 0; kc < 8; kc++) {
        cp_wait0();
        __syncthreads();
        if (kc < 7)
            prefetch_chunk(g_Wc_f + (kc + 1) * 2048, bbase + ((kc + 1) & 1) * 16384, tid);
        gemm_chunk2(acc, ah_u, al_u, Bbuf + (kc & 1) * 2048, kc * 32, mg, ng, lane);
    }
    __syncthreads();   // A reads done; emb may alias A region

    // ---- epilogue: emb = pol*(h2 + bc) + bl -> smem (aliases A, stride 260) ----
    float* emb = (float*)smem;     // [128][EMB_STRIDE] = 133120 B <= 135168 B
    #pragma unroll
    for (int mt = 0; mt < 4; mt++) {
        int r0 = mg * 64 + mt * 16 + nr, r1 = r0 + 8;
        float p0 = pol[r0], p1 = pol[r1];
        #pragma unroll
        for (int ni = 0; ni < 8; ni++) {
            int c = ng * 64 + ni * 8 + kq * 2;
            float2 bcv = *(const float2*)&bcs[c];
            float2 blv = *(const float2*)&bls[c];
            *(float2*)&emb[r0 * EMB_STRIDE + c] =
                make_float2(p0 * (acc[mt][ni][0] + bcv.x) + blv.x,
                            p0 * (acc[mt][ni][1] + bcv.y) + blv.y);
            *(float2*)&emb[r1 * EMB_STRIDE + c] =
                make_float2(p1 * (acc[mt][ni][2] + bcv.x) + blv.x,
                            p1 * (acc[mt][ni][3] + bcv.y) + blv.y);
        }
    }
    __syncthreads();

    // ---- gather x[src], msg = relu(x+emb), scatter-add ----
    #pragma unroll
    for (int it = 0; it < 16; it++) {
        int r = it * 8 + warp;
        int si = srcs[r], di = dsts[r];
        const float4* xp = (const float4*)(x + (size_t)si * D);
        float* ap = &g_aggr[(size_t)di * D];
        #pragma unroll
        for (int seg = 0; seg < 2; seg++) {
            int c4 = lane + seg * 32;
            float4 ee = *(const float4*)&emb[r * EMB_STRIDE + c4 * 4];
            float4 xv = xp[c4];
            float4 m;
            m.x = fmaxf(xv.x + ee.x, 0.f);
            m.y = fmaxf(xv.y + ee.y, 0.f);
            m.z = fmaxf(xv.z + ee.z, 0.f);
            m.w = fmaxf(xv.w + ee.w, 0.f);
            red_add_v4(ap + c4 * 4, m);
        }
    }
}

// ---------------- node kernel ----------------
#define N_AH   0
#define N_AL   67584
#define N_B    135168      // 2 x 16384
#define N_PS   167936      // float2 ps[128][4] = 4096
#define N_SML  172032      // bg1 | lng | lnb | bg2 (4 x 1024)
#define NODE_SMEM_BYTES 176128

__global__ __launch_bounds__(256, 1) void node_kernel(
    const float* __restrict__ x,
    const float* __restrict__ b_g1,
    const float* __restrict__ ln_g,
    const float* __restrict__ ln_b,
    const float* __restrict__ b_g2,
    float* __restrict__ out)
{
    extern __shared__ char smem[];
    __half* Ah = (__half*)(smem + N_AH);
    __half* Al = (__half*)(smem + N_AL);
    uint2* Bbuf = (uint2*)(smem + N_B);
    float2* ps  = (float2*)(smem + N_PS);    // [128 rows][4 ngroups]
    float* bg1 = (float*)(smem + N_SML);
    float* lng = (float*)(smem + N_SML + 1024);
    float* lnb = (float*)(smem + N_SML + 2048);
    float* bg2 = (float*)(smem + N_SML + 3072);

    const int tid  = threadIdx.x;
    const int lane = tid & 31;
    const int warp = tid >> 5;
    const int mg   = warp >> 2;
    const int ng   = warp & 3;
    const int nr   = lane >> 2, kq = lane & 3;
    const int n0   = blockIdx.x * TN;
    const uint32_t ah_u = smem_u32(Ah), al_u = smem_u32(Al);
    const uint32_t bbase = smem_u32(smem + N_B);

    prefetch_chunk(g_Wg1_f, bbase, tid);

    // stage xin = x + aggr, split
    for (int i = tid; i < TN * D; i += 256) {
        int n = i >> 8, d = i & 255;
        int g = n0 + n;
        float v = 0.f;
        if (g < N_NODES) v = x[(size_t)g * D + d] + g_aggr[(size_t)g * D + d];
        __half h = __float2half_rn(v);
        Ah[n * 264 + d] = h;
        Al[n * 264 + d] = __float2half_rn(v - __half2float(h));
    }
    bg1[tid] = b_g1[tid];
    lng[tid] = ln_g[tid];
    lnb[tid] = ln_b[tid];
    bg2[tid] = b_g2[tid];

    float acc[4][8][4];
    #pragma unroll
    for (int a = 0; a < 4; a++)
        #pragma unroll
        for (int b = 0; b < 8; b++)
            #pragma unroll
            for (int c = 0; c < 4; c++) acc[a][b][c] = 0.f;

    // ---- GEMM1 ----
    #pragma unroll 1
    for (int kc = 0; kc < 8; kc++) {
        cp_wait0();
        __syncthreads();
        if (kc < 7) prefetch_chunk(g_Wg1_f + (kc + 1) * 2048, bbase + ((kc + 1) & 1) * 16384, tid);
        else        prefetch_chunk(g_Wg2_f, bbase, tid);       // chain into GEMM2
        gemm_chunk2(acc, ah_u, al_u, Bbuf + (kc & 1) * 2048, kc * 32, mg, ng, lane);
    }

    // ---- bias + partial LN stats (per-warp 64-col partials) ----
    #pragma unroll
    for (int mt = 0; mt < 4; mt++) {
        float sl = 0.f, ql = 0.f, sh = 0.f, qh = 0.f;
        #pragma unroll
        for (int ni = 0; ni < 8; ni++) {
            int c = ng * 64 + ni * 8 + kq * 2;
            float2 b = *(const float2*)&bg1[c];
            float v0 = acc[mt][ni][0] + b.x, v1 = acc[mt][ni][1] + b.y;
            float v2 = acc[mt][ni][2] + b.x, v3 = acc[mt][ni][3] + b.y;
            acc[mt][ni][0] = v0; acc[mt][ni][1] = v1;
            acc[mt][ni][2] = v2; acc[mt][ni][3] = v3;
            sl += v0 + v1; ql += v0 * v0 + v1 * v1;
            sh += v2 + v3; qh += v2 * v2 + v3 * v3;
        }
        #pragma unroll
        for (int off = 1; off <= 2; off <<= 1) {
            sl += __shfl_xor_sync(0xffffffffu, sl, off);
            ql += __shfl_xor_sync(0xffffffffu, ql, off);
            sh += __shfl_xor_sync(0xffffffffu, sh, off);
            qh += __shfl_xor_sync(0xffffffffu, qh, off);
        }
        if (kq == 0) {
            int r0 = mg * 64 + mt * 16 + nr;
            ps[r0 * 4 + ng]       = make_float2(sl, ql);
            ps[(r0 + 8) * 4 + ng] = make_float2(sh, qh);
        }
    }
    __syncthreads();

    // full stats per row, normalize + relu + split -> A (overwrites xin)
    float mu[4][2], rs[4][2];
    #pragma unroll
    for (int mt = 0; mt < 4; mt++) {
        int r0 = mg * 64 + mt * 16 + nr;
        #pragma unroll
        for (int h = 0; h < 2; h++) {
            float s = 0.f, q = 0.f;
            #pragma unroll
            for (int g = 0; g < 4; g++) {
                float2 p = ps[(r0 + h * 8) * 4 + g];
                s += p.x; q += p.y;
            }
            float m = s * (1.f / D);
            float v = q * (1.f / D) - m * m;
            mu[mt][h] = m;
            rs[mt][h] = rsqrtf(v + LN_EPS);
        }
    }
    #pragma unroll
    for (int mt = 0; mt < 4; mt++) {
        int r0 = mg * 64 + mt * 16 + nr, r1 = r0 + 8;
        #pragma unroll
        for (int ni = 0; ni < 8; ni++) {
            int c = ng * 64 + ni * 8 + kq * 2;
            float2 g = *(const float2*)&lng[c];
            float2 bb = *(const float2*)&lnb[c];
            float v0 = fmaxf((acc[mt][ni][0] - mu[mt][0]) * rs[mt][0] * g.x + bb.x, 0.f);
            float v1 = fmaxf((acc[mt][ni][1] - mu[mt][0]) * rs[mt][0] * g.y + bb.y, 0.f);
            float v2 = fmaxf((acc[mt][ni][2] - mu[mt][1]) * rs[mt][1] * g.x + bb.x, 0.f);
            float v3 = fmaxf((acc[mt][ni][3] - mu[mt][1]) * rs[mt][1] * g.y + bb.y, 0.f);
            uint32_t hi, lo;
            splitpack(v0, v1, hi, lo);
            *(uint32_t*)&Ah[r0 * 264 + c] = hi;
            *(uint32_t*)&Al[r0 * 264 + c] = lo;
            splitpack(v2, v3, hi, lo);
            *(uint32_t*)&Ah[r1 * 264 + c] = hi;
            *(uint32_t*)&Al[r1 * 264 + c] = lo;
            acc[mt][ni][0] = acc[mt][ni][1] = acc[mt][ni][2] = acc[mt][ni][3] = 0.f;
        }
    }

    // ---- GEMM2 (first sync inside loop orders the A stores above) ----
    #pragma unroll 1
    for (int kc = 0; kc < 8; kc++) {
        cp_wait0();
        __syncthreads();
        if (kc < 7) prefetch_chunk(g_Wg2_f + (kc + 1) * 2048, bbase + ((kc + 1) & 1) * 16384, tid);
        gemm_chunk2(acc, ah_u, al_u, Bbuf + (kc & 1) * 2048, kc * 32, mg, ng, lane);
    }

    // ---- epilogue: + b_g2 -> out ----
    #pragma unroll
    for (int mt = 0; mt < 4; mt++) {
        int r0 = mg * 64 + mt * 16 + nr, r1 = r0 + 8;
        int gr0 = n0 + r0, gr1 = n0 + r1;
        #pragma unroll
        for (int ni = 0; ni < 8; ni++) {
            int c = ng * 64 + ni * 8 + kq * 2;
            float2 b = *(const float2*)&bg2[c];
            if (gr0 < N_NODES)
                *(float2*)&out[(size_t)gr0 * D + c] =
                    make_float2(acc[mt][ni][0] + b.x, acc[mt][ni][1] + b.y);
            if (gr1 < N_NODES)
                *(float2*)&out[(size_t)gr1 * D + c] =
                    make_float2(acc[mt][ni][2] + b.x, acc[mt][ni][3] + b.y);
        }
    }
}

// ---------------- launch ----------------
extern "C" void kernel_launch(void* const* d_in, const int* in_sizes, int n_in,
                              void* d_out, int out_size)
{
    const float* x         = (const float*)d_in[0];
    const void*  eidx      = d_in[1];
    const float* edge_attr = (const float*)d_in[2];
    const float* W_e1      = (const float*)d_in[3];
    const float* b_e1      = (const float*)d_in[4];
    const float* W_e2      = (const float*)d_in[5];
    const float* b_e2      = (const float*)d_in[6];
    const float* W_le      = (const float*)d_in[7];
    const float* b_le      = (const float*)d_in[8];
    const float* W_g1      = (const float*)d_in[9];
    const float* b_g1      = (const float*)d_in[10];
    const float* ln_g      = (const float*)d_in[11];
    const float* ln_b      = (const float*)d_in[12];
    const float* W_g2      = (const float*)d_in[13];
    const float* b_g2      = (const float*)d_in[14];
    float*       out       = (float*)d_out;

    cudaFuncSetAttribute(edge_kernel, cudaFuncAttributeMaxDynamicSharedMemorySize, EDGE_SMEM_BYTES);
    cudaFuncSetAttribute(node_kernel, cudaFuncAttributeMaxDynamicSharedMemorySize, NODE_SMEM_BYTES);

    detect_idx_kernel<<<1, 256>>>((const int*)eidx);
    convert_idx_kernel<<<(N_EDGES + 255) / 256, 256>>>(eidx);

    prep_Wc<<<64, 256>>>(W_le, W_e2);
    prep_bc<<<256, 256>>>(W_le, b_e2);
    pack_frags<<<208, 256>>>(W_e1, W_g1, W_g2);
    zero_aggr<<<(N_NODES * D / 4 + 255) / 256, 256>>>();

    edge_kernel<<<N_EDGES / TE, 256, EDGE_SMEM_BYTES>>>(x, edge_attr, b_e1, b_le);
    node_kernel<<<(N_NODES + TN - 1) / TN, 256, NODE_SMEM_BYTES>>>(x, b_g1, ln_g, ln_b, b_g2, out);
}

// round 10
// speedup vs baseline: 6.2012x; 1.1884x over previous
#include <cuda_runtime.h>
#include <cuda_bf16.h>
#include <cuda_fp16.h>
#include <stdint.h>

#define N_NODES 50000
#define N_EDGES 800000
#define D 256
#define F 64
#define LN_EPS 1e-5f
#define TE 64
#define TN 64

// ---------------- device scratch ----------------
__device__ float g_Wc[D * D];            // fp32 (W_le @ W_e2), [n][k]
__device__ float g_bc[D];                // W_le @ b_e2
// fragment-packed fp16 weights (hi only): [k16-slice][ntile(32)][lane(32)] = {h0,h1}
__device__ uint2 g_We1_f[4 * 1024];      // K=64  -> 4 slices
__device__ uint2 g_Wc_f[16 * 1024];      // K=256 -> 16 slices
__device__ uint2 g_Wg1_f[16 * 1024];
__device__ uint2 g_Wg2_f[16 * 1024];
__device__ __align__(16) float g_aggr[(size_t)N_NODES * D];
__device__ int g_idx_is64;
__device__ int g_srcs[N_EDGES], g_dsts[N_EDGES];

// ---------------- low-level helpers ----------------
__device__ __forceinline__ void red_add_v4(float* p, float4 v) {
    asm volatile("red.global.add.v4.f32 [%0], {%1,%2,%3,%4};"
                 :: "l"(p), "f"(v.x), "f"(v.y), "f"(v.z), "f"(v.w) : "memory");
}
__device__ __forceinline__ uint32_t smem_u32(const void* p) {
    return (uint32_t)__cvta_generic_to_shared(p);
}
__device__ __forceinline__ void cpasync16(uint32_t dst, const void* src) {
    asm volatile("cp.async.cg.shared.global [%0], [%1], 16;" :: "r"(dst), "l"(src));
}
__device__ __forceinline__ void cp_commit() { asm volatile("cp.async.commit_group;"); }
__device__ __forceinline__ void cp_wait0()  { asm volatile("cp.async.wait_group 0;"); }

__device__ __forceinline__ void ldsm4(uint32_t* r, uint32_t addr) {
    asm volatile("ldmatrix.sync.aligned.m8n8.x4.shared.b16 {%0,%1,%2,%3}, [%4];"
                 : "=r"(r[0]), "=r"(r[1]), "=r"(r[2]), "=r"(r[3]) : "r"(addr));
}
__device__ __forceinline__ void mma_f16(float* c,
    uint32_t a0, uint32_t a1, uint32_t a2, uint32_t a3, uint32_t b0, uint32_t b1) {
    asm volatile("mma.sync.aligned.m16n8k16.row.col.f32.f16.f16.f32 "
                 "{%0,%1,%2,%3}, {%4,%5,%6,%7}, {%8,%9}, {%0,%1,%2,%3};"
                 : "+f"(c[0]), "+f"(c[1]), "+f"(c[2]), "+f"(c[3])
                 : "r"(a0), "r"(a1), "r"(a2), "r"(a3), "r"(b0), "r"(b1));
}
// fp16 hi/lo split of two fp32 values, packed
__device__ __forceinline__ void splitpack(float a, float b, uint32_t& hi, uint32_t& lo) {
    __half ha = __float2half_rn(a), hb = __float2half_rn(b);
    __half la = __float2half_rn(a - __half2float(ha));
    __half lb = __float2half_rn(b - __half2float(hb));
    hi = (uint32_t)__half_as_ushort(ha) | ((uint32_t)__half_as_ushort(hb) << 16);
    lo = (uint32_t)__half_as_ushort(la) | ((uint32_t)__half_as_ushort(lb) << 16);
}
__device__ __forceinline__ uint32_t pack_f16hi(float a, float b) {
    return (uint32_t)__half_as_ushort(__float2half_rn(a)) |
           ((uint32_t)__half_as_ushort(__float2half_rn(b)) << 16);
}

// contiguous 16KB chunk (2 k16-slices, hi-only) of fragment-packed B -> smem
__device__ __forceinline__ void prefetch_chunk(const uint2* __restrict__ gsrc,
                                               uint32_t b_base, int tid) {
    const uint4* g4 = (const uint4*)gsrc;
    #pragma unroll
    for (int t = 0; t < 4; t++) {
        int i = tid + t * 256;          // 1024 x 16B = 16 KB
        cpasync16(b_base + (uint32_t)i * 16, g4 + i);
    }
    cp_commit();
}

// one 32-k chunk: warp tile 32x64, A hi/lo fp16 from smem (stride 264), B hi-only
__device__ __forceinline__ void gemm_chunk2(float acc[2][8][4],
    uint32_t ah_u, uint32_t al_u, const uint2* __restrict__ B,
    int k0base, int mg, int ng, int lane)
{
    #pragma unroll
    for (int s = 0; s < 2; s++) {
        uint32_t ahi[2][4], alo[2][4];
        int col = k0base + s * 16 + ((lane >> 4) << 3);
        #pragma unroll
        for (int mt = 0; mt < 2; mt++) {
            int row = mg * 32 + mt * 16 + (lane & 15);
            ldsm4(ahi[mt], ah_u + (uint32_t)(row * 264 + col) * 2);
            ldsm4(alo[mt], al_u + (uint32_t)(row * 264 + col) * 2);
        }
        #pragma unroll
        for (int ni = 0; ni < 8; ni++) {
            uint2 f = B[(s * 32 + ng * 8 + ni) * 32 + lane];
            #pragma unroll
            for (int mt = 0; mt < 2; mt++) {
                mma_f16(acc[mt][ni], ahi[mt][0], ahi[mt][1], ahi[mt][2], ahi[mt][3], f.x, f.y);
                mma_f16(acc[mt][ni], alo[mt][0], alo[mt][1], alo[mt][2], alo[mt][3], f.x, f.y);
            }
        }
    }
}

// ---------------- index handling (proven) ----------------
__global__ void detect_idx_kernel(const int* __restrict__ p) {
    __shared__ int acc[256];
    int t = threadIdx.x;
    int v = 0;
    #pragma unroll
    for (int i = 0; i < 4; i++) v |= p[(t * 4 + i) * 2 + 1];
    acc[t] = v;
    __syncthreads();
    for (int s = 128; s; s >>= 1) { if (t < s) acc[t] |= acc[t + s]; __syncthreads(); }
    if (t == 0) g_idx_is64 = (acc[0] == 0) ? 1 : 0;
}
__global__ void convert_idx_kernel(const void* __restrict__ eidx) {
    int i = blockIdx.x * blockDim.x + threadIdx.x;
    if (i >= N_EDGES) return;
    int s, d;
    if (g_idx_is64) {
        const long long* p = (const long long*)eidx;
        s = (int)p[i]; d = (int)p[(size_t)N_EDGES + i];
    } else {
        const int* p = (const int*)eidx;
        s = p[i]; d = p[N_EDGES + i];
    }
    g_srcs[i] = min(max(s, 0), N_NODES - 1);
    g_dsts[i] = min(max(d, 0), N_NODES - 1);
}

// ---------------- prep kernels ----------------
__global__ void prep_Wc(const float* __restrict__ W_le, const float* __restrict__ W_e2) {
    __shared__ float wle[4][256];
    int b = blockIdx.x, t = threadIdx.x;       // 64 blocks
    #pragma unroll
    for (int r = 0; r < 4; r++) wle[r][t] = W_le[(b * 4 + r) * 256 + t];
    __syncthreads();
    float a0 = 0, a1 = 0, a2 = 0, a3 = 0;
    #pragma unroll 4
    for (int j = 0; j < 256; j++) {
        float w = W_e2[j * 256 + t];
        a0 += wle[0][j] * w; a1 += wle[1][j] * w;
        a2 += wle[2][j] * w; a3 += wle[3][j] * w;
    }
    g_Wc[(b * 4 + 0) * 256 + t] = a0;
    g_Wc[(b * 4 + 1) * 256 + t] = a1;
    g_Wc[(b * 4 + 2) * 256 + t] = a2;
    g_Wc[(b * 4 + 3) * 256 + t] = a3;
}
__global__ void prep_bc(const float* __restrict__ W_le, const float* __restrict__ b_e2) {
    __shared__ float red[256];
    int d = blockIdx.x, t = threadIdx.x;       // 256 blocks
    red[t] = W_le[d * 256 + t] * b_e2[t];
    __syncthreads();
    for (int s = 128; s; s >>= 1) { if (t < s) red[t] += red[t + s]; __syncthreads(); }
    if (t == 0) g_bc[d] = red[0];
}
// pack all weights into mma-fragment order (fp16 hi only)
__global__ void pack_frags(const float* __restrict__ We1,
                           const float* __restrict__ Wg1,
                           const float* __restrict__ Wg2) {
    int id = blockIdx.x * 256 + threadIdx.x;     // 53248 total
    const float* W; uint2* dst; int K, rel;
    if (id < 4096)       { W = We1;  dst = g_We1_f; K = 64;  rel = id; }
    else if (id < 20480) { W = g_Wc; dst = g_Wc_f;  K = 256; rel = id - 4096; }
    else if (id < 36864) { W = Wg1;  dst = g_Wg1_f; K = 256; rel = id - 20480; }
    else                 { W = Wg2;  dst = g_Wg2_f; K = 256; rel = id - 36864; }
    int slice = rel >> 10, idx = rel & 1023, nt = idx >> 5, lane = idx & 31;
    int nr = lane >> 2, kq = lane & 3;
    int n = nt * 8 + nr, k0 = slice * 16 + kq * 2;
    uint32_t h0 = pack_f16hi(W[n * K + k0],     W[n * K + k0 + 1]);
    uint32_t h1 = pack_f16hi(W[n * K + k0 + 8], W[n * K + k0 + 9]);
    dst[rel] = make_uint2(h0, h1);
}
__global__ void zero_aggr() {
    size_t i = (size_t)blockIdx.x * blockDim.x + threadIdx.x;
    if (i < (size_t)N_NODES * D / 4)
        ((float4*)g_aggr)[i] = make_float4(0.f, 0.f, 0.f, 0.f);
}

// ---------------- edge kernel (64 edges/block, 2 CTAs/SM) ----------------
#define E_AH   0           // fp16 [64][264] = 33792
#define E_AL   33792
#define E_B    67584       // 2 x 16384
#define E_SML  100352      // pol 256 | srcs 256 | dsts 256 | bcs 1024 | bls 1024 | be1s 1024
#define EDGE_SMEM_BYTES 104192
#define EMB_STRIDE 260     // fp32 row stride for emb staging (1040B pitch, 16B-aligned)

__global__ __launch_bounds__(256, 2) void edge_kernel(
    const float* __restrict__ x,
    const float* __restrict__ edge_attr,
    const float* __restrict__ b_e1,
    const float* __restrict__ b_le)
{
    extern __shared__ char smem[];
    __half* Ah = (__half*)(smem + E_AH);
    __half* Al = (__half*)(smem + E_AL);
    uint2* Bbuf = (uint2*)(smem + E_B);
    float* pol  = (float*)(smem + E_SML);
    int*   srcs = (int*)(smem + E_SML + 256);
    int*   dsts = (int*)(smem + E_SML + 512);
    float* bcs  = (float*)(smem + E_SML + 768);
    float* bls  = (float*)(smem + E_SML + 1792);
    float* be1s = (float*)(smem + E_SML + 2816);

    const int tid  = threadIdx.x;
    const int lane = tid & 31;
    const int warp = tid >> 5;
    const int mg   = warp >> 2;     // 0..1 (row group of 32)
    const int ng   = warp & 3;      // 0..3 (col group of 64)
    const int nr   = lane >> 2, kq = lane & 3;
    const int e0   = blockIdx.x * TE;
    const uint32_t ah_u = smem_u32(Ah), al_u = smem_u32(Al);
    const uint32_t bbase = smem_u32(smem + E_B);

    prefetch_chunk(g_We1_f, bbase, tid);          // GEMM1 chunk0 -> buf0

    // stage raw split into A cols 0..63
    #pragma unroll
    for (int t = 0; t < 16; t++) {
        int i = tid + t * 256;          // 64*64
        int e = i >> 6, k = i & 63;
        float v = edge_attr[(size_t)(e0 + e) * 65 + 1 + k];
        __half h = __float2half_rn(v);
        Ah[e * 264 + k] = h;
        Al[e * 264 + k] = __float2half_rn(v - __half2float(h));
    }
    if (tid < TE) {
        float p = edge_attr[(size_t)(e0 + tid) * 65];
        pol[tid] = fminf(fmaxf(p, 0.f), 1.f) + 0.01f;
        srcs[tid] = g_srcs[e0 + tid];
        dsts[tid] = g_dsts[e0 + tid];
    }
    bcs[tid]  = g_bc[tid];
    bls[tid]  = b_le[tid];
    be1s[tid] = b_e1[tid];

    float acc[2][8][4];
    #pragma unroll
    for (int a = 0; a < 2; a++)
        #pragma unroll
        for (int b = 0; b < 8; b++)
            #pragma unroll
            for (int c = 0; c < 4; c++) acc[a][b][c] = 0.f;

    // ---- GEMM1: h1 = raw @ We1^T (K=64, 2 chunks) ----
    #pragma unroll
    for (int kc = 0; kc < 2; kc++) {
        cp_wait0();
        __syncthreads();
        if (kc == 0) prefetch_chunk(g_We1_f + 2048, bbase + 16384, tid);
        else         prefetch_chunk(g_Wc_f, bbase, tid);        // GEMM2 chunk0 -> buf0
        gemm_chunk2(acc, ah_u, al_u, Bbuf + (kc & 1) * 2048, kc * 32, mg, ng, lane);
    }
    __syncthreads();   // all raw reads done before overwrite

    // ---- h1 = relu(acc + b_e1), split, store back into A (cols = GEMM2 k) ----
    #pragma unroll
    for (int mt = 0; mt < 2; mt++) {
        int r0 = mg * 32 + mt * 16 + nr, r1 = r0 + 8;
        #pragma unroll
        for (int ni = 0; ni < 8; ni++) {
            int c = ng * 64 + ni * 8 + kq * 2;
            float2 b = *(const float2*)&be1s[c];
            float v0 = fmaxf(acc[mt][ni][0] + b.x, 0.f);
            float v1 = fmaxf(acc[mt][ni][1] + b.y, 0.f);
            float v2 = fmaxf(acc[mt][ni][2] + b.x, 0.f);
            float v3 = fmaxf(acc[mt][ni][3] + b.y, 0.f);
            uint32_t hi, lo;
            splitpack(v0, v1, hi, lo);
            *(uint32_t*)&Ah[r0 * 264 + c] = hi;
            *(uint32_t*)&Al[r0 * 264 + c] = lo;
            splitpack(v2, v3, hi, lo);
            *(uint32_t*)&Ah[r1 * 264 + c] = hi;
            *(uint32_t*)&Al[r1 * 264 + c] = lo;
            acc[mt][ni][0] = acc[mt][ni][1] = acc[mt][ni][2] = acc[mt][ni][3] = 0.f;
        }
    }

    // ---- GEMM2: h2 = h1 @ Wc^T (K=256, 8 chunks, single stream) ----
    #pragma unroll 1
    for (int kc = 0; kc < 8; kc++) {
        cp_wait0();
        __syncthreads();
        if (kc < 7)
            prefetch_chunk(g_Wc_f + (kc + 1) * 2048, bbase + ((kc + 1) & 1) * 16384, tid);
        gemm_chunk2(acc, ah_u, al_u, Bbuf + (kc & 1) * 2048, kc * 32, mg, ng, lane);
    }
    __syncthreads();   // A reads done; emb may alias A region

    // ---- epilogue: emb = pol*(h2 + bc) + bl -> smem (aliases A, stride 260) ----
    float* emb = (float*)smem;     // [64][EMB_STRIDE] = 66560 B <= 67584 B
    #pragma unroll
    for (int mt = 0; mt < 2; mt++) {
        int r0 = mg * 32 + mt * 16 + nr, r1 = r0 + 8;
        float p0 = pol[r0], p1 = pol[r1];
        #pragma unroll
        for (int ni = 0; ni < 8; ni++) {
            int c = ng * 64 + ni * 8 + kq * 2;
            float2 bcv = *(const float2*)&bcs[c];
            float2 blv = *(const float2*)&bls[c];
            *(float2*)&emb[r0 * EMB_STRIDE + c] =
                make_float2(p0 * (acc[mt][ni][0] + bcv.x) + blv.x,
                            p0 * (acc[mt][ni][1] + bcv.y) + blv.y);
            *(float2*)&emb[r1 * EMB_STRIDE + c] =
                make_float2(p1 * (acc[mt][ni][2] + bcv.x) + blv.x,
                            p1 * (acc[mt][ni][3] + bcv.y) + blv.y);
        }
    }
    __syncthreads();

    // ---- gather x[src], msg = relu(x+emb), scatter-add ----
    #pragma unroll
    for (int it = 0; it < 8; it++) {
        int r = it * 8 + warp;
        int si = srcs[r], di = dsts[r];
        const float4* xp = (const float4*)(x + (size_t)si * D);
        float* ap = &g_aggr[(size_t)di * D];
        #pragma unroll
        for (int seg = 0; seg < 2; seg++) {
            int c4 = lane + seg * 32;
            float4 ee = *(const float4*)&emb[r * EMB_STRIDE + c4 * 4];
            float4 xv = xp[c4];
            float4 m;
            m.x = fmaxf(xv.x + ee.x, 0.f);
            m.y = fmaxf(xv.y + ee.y, 0.f);
            m.z = fmaxf(xv.z + ee.z, 0.f);
            m.w = fmaxf(xv.w + ee.w, 0.f);
            red_add_v4(ap + c4 * 4, m);
        }
    }
}

// ---------------- node kernel (64 nodes/block, 2 CTAs/SM) ----------------
#define N_AH   0
#define N_AL   33792
#define N_B    67584       // 2 x 16384
#define N_PS   100352      // float2 ps[64][4] = 2048
#define N_SML  102400      // bg1 | lng | lnb | bg2 (4 x 1024)
#define NODE_SMEM_BYTES 106496

__global__ __launch_bounds__(256, 2) void node_kernel(
    const float* __restrict__ x,
    const float* __restrict__ b_g1,
    const float* __restrict__ ln_g,
    const float* __restrict__ ln_b,
    const float* __restrict__ b_g2,
    float* __restrict__ out)
{
    extern __shared__ char smem[];
    __half* Ah = (__half*)(smem + N_AH);
    __half* Al = (__half*)(smem + N_AL);
    uint2* Bbuf = (uint2*)(smem + N_B);
    float2* ps  = (float2*)(smem + N_PS);    // [64 rows][4 ngroups]
    float* bg1 = (float*)(smem + N_SML);
    float* lng = (float*)(smem + N_SML + 1024);
    float* lnb = (float*)(smem + N_SML + 2048);
    float* bg2 = (float*)(smem + N_SML + 3072);

    const int tid  = threadIdx.x;
    const int lane = tid & 31;
    const int warp = tid >> 5;
    const int mg   = warp >> 2;
    const int ng   = warp & 3;
    const int nr   = lane >> 2, kq = lane & 3;
    const int n0   = blockIdx.x * TN;
    const uint32_t ah_u = smem_u32(Ah), al_u = smem_u32(Al);
    const uint32_t bbase = smem_u32(smem + N_B);

    prefetch_chunk(g_Wg1_f, bbase, tid);

    // stage xin = x + aggr, split
    for (int i = tid; i < TN * D; i += 256) {
        int n = i >> 8, d = i & 255;
        int g = n0 + n;
        float v = 0.f;
        if (g < N_NODES) v = x[(size_t)g * D + d] + g_aggr[(size_t)g * D + d];
        __half h = __float2half_rn(v);
        Ah[n * 264 + d] = h;
        Al[n * 264 + d] = __float2half_rn(v - __half2float(h));
    }
    bg1[tid] = b_g1[tid];
    lng[tid] = ln_g[tid];
    lnb[tid] = ln_b[tid];
    bg2[tid] = b_g2[tid];

    float acc[2][8][4];
    #pragma unroll
    for (int a = 0; a < 2; a++)
        #pragma unroll
        for (int b = 0; b < 8; b++)
            #pragma unroll
            for (int c = 0; c < 4; c++) acc[a][b][c] = 0.f;

    // ---- GEMM1 ----
    #pragma unroll 1
    for (int kc = 0; kc < 8; kc++) {
        cp_wait0();
        __syncthreads();
        if (kc < 7) prefetch_chunk(g_Wg1_f + (kc + 1) * 2048, bbase + ((kc + 1) & 1) * 16384, tid);
        else        prefetch_chunk(g_Wg2_f, bbase, tid);       // chain into GEMM2
        gemm_chunk2(acc, ah_u, al_u, Bbuf + (kc & 1) * 2048, kc * 32, mg, ng, lane);
    }

    // ---- bias + partial LN stats (per-warp 64-col partials) ----
    #pragma unroll
    for (int mt = 0; mt < 2; mt++) {
        float sl = 0.f, ql = 0.f, sh = 0.f, qh = 0.f;
        #pragma unroll
        for (int ni = 0; ni < 8; ni++) {
            int c = ng * 64 + ni * 8 + kq * 2;
            float2 b = *(const float2*)&bg1[c];
            float v0 = acc[mt][ni][0] + b.x, v1 = acc[mt][ni][1] + b.y;
            float v2 = acc[mt][ni][2] + b.x, v3 = acc[mt][ni][3] + b.y;
            acc[mt][ni][0] = v0; acc[mt][ni][1] = v1;
            acc[mt][ni][2] = v2; acc[mt][ni][3] = v3;
            sl += v0 + v1; ql += v0 * v0 + v1 * v1;
            sh += v2 + v3; qh += v2 * v2 + v3 * v3;
        }
        #pragma unroll
        for (int off = 1; off <= 2; off <<= 1) {
            sl += __shfl_xor_sync(0xffffffffu, sl, off);
            ql += __shfl_xor_sync(0xffffffffu, ql, off);
            sh += __shfl_xor_sync(0xffffffffu, sh, off);
            qh += __shfl_xor_sync(0xffffffffu, qh, off);
        }
        if (kq == 0) {
            int r0 = mg * 32 + mt * 16 + nr;
            ps[r0 * 4 + ng]       = make_float2(sl, ql);
            ps[(r0 + 8) * 4 + ng] = make_float2(sh, qh);
        }
    }
    __syncthreads();

    // full stats per row, normalize + relu + split -> A (overwrites xin)
    float mu[2][2], rs[2][2];
    #pragma unroll
    for (int mt = 0; mt < 2; mt++) {
        int r0 = mg * 32 + mt * 16 + nr;
        #pragma unroll
        for (int h = 0; h < 2; h++) {
            float s = 0.f, q = 0.f;
            #pragma unroll
            for (int g = 0; g < 4; g++) {
                float2 p = ps[(r0 + h * 8) * 4 + g];
                s += p.x; q += p.y;
            }
            float m = s * (1.f / D);
            float v = q * (1.f / D) - m * m;
            mu[mt][h] = m;
            rs[mt][h] = rsqrtf(v + LN_EPS);
        }
    }
    #pragma unroll
    for (int mt = 0; mt < 2; mt++) {
        int r0 = mg * 32 + mt * 16 + nr, r1 = r0 + 8;
        #pragma unroll
        for (int ni = 0; ni < 8; ni++) {
            int c = ng * 64 + ni * 8 + kq * 2;
            float2 g = *(const float2*)&lng[c];
            float2 bb = *(const float2*)&lnb[c];
            float v0 = fmaxf((acc[mt][ni][0] - mu[mt][0]) * rs[mt][0] * g.x + bb.x, 0.f);
            float v1 = fmaxf((acc[mt][ni][1] - mu[mt][0]) * rs[mt][0] * g.y + bb.y, 0.f);
            float v2 = fmaxf((acc[mt][ni][2] - mu[mt][1]) * rs[mt][1] * g.x + bb.x, 0.f);
            float v3 = fmaxf((acc[mt][ni][3] - mu[mt][1]) * rs[mt][1] * g.y + bb.y, 0.f);
            uint32_t hi, lo;
            splitpack(v0, v1, hi, lo);
            *(uint32_t*)&Ah[r0 * 264 + c] = hi;
            *(uint32_t*)&Al[r0 * 264 + c] = lo;
            splitpack(v2, v3, hi, lo);
            *(uint32_t*)&Ah[r1 * 264 + c] = hi;
            *(uint32_t*)&Al[r1 * 264 + c] = lo;
            acc[mt][ni][0] = acc[mt][ni][1] = acc[mt][ni][2] = acc[mt][ni][3] = 0.f;
        }
    }

    // ---- GEMM2 (first sync inside loop orders the A stores above) ----
    #pragma unroll 1
    for (int kc = 0; kc < 8; kc++) {
        cp_wait0();
        __syncthreads();
        if (kc < 7) prefetch_chunk(g_Wg2_f + (kc + 1) * 2048, bbase + ((kc + 1) & 1) * 16384, tid);
        gemm_chunk2(acc, ah_u, al_u, Bbuf + (kc & 1) * 2048, kc * 32, mg, ng, lane);
    }

    // ---- epilogue: + b_g2 -> out ----
    #pragma unroll
    for (int mt = 0; mt < 2; mt++) {
        int r0 = mg * 32 + mt * 16 + nr, r1 = r0 + 8;
        int gr0 = n0 + r0, gr1 = n0 + r1;
        #pragma unroll
        for (int ni = 0; ni < 8; ni++) {
            int c = ng * 64 + ni * 8 + kq * 2;
            float2 b = *(const float2*)&bg2[c];
            if (gr0 < N_NODES)
                *(float2*)&out[(size_t)gr0 * D + c] =
                    make_float2(acc[mt][ni][0] + b.x, acc[mt][ni][1] + b.y);
            if (gr1 < N_NODES)
                *(float2*)&out[(size_t)gr1 * D + c] =
                    make_float2(acc[mt][ni][2] + b.x, acc[mt][ni][3] + b.y);
        }
    }
}

// ---------------- launch ----------------
extern "C" void kernel_launch(void* const* d_in, const int* in_sizes, int n_in,
                              void* d_out, int out_size)
{
    const float* x         = (const float*)d_in[0];
    const void*  eidx      = d_in[1];
    const float* edge_attr = (const float*)d_in[2];
    const float* W_e1      = (const float*)d_in[3];
    const float* b_e1      = (const float*)d_in[4];
    const float* W_e2      = (const float*)d_in[5];
    const float* b_e2      = (const float*)d_in[6];
    const float* W_le      = (const float*)d_in[7];
    const float* b_le      = (const float*)d_in[8];
    const float* W_g1      = (const float*)d_in[9];
    const float* b_g1      = (const float*)d_in[10];
    const float* ln_g      = (const float*)d_in[11];
    const float* ln_b      = (const float*)d_in[12];
    const float* W_g2      = (const float*)d_in[13];
    const float* b_g2      = (const float*)d_in[14];
    float*       out       = (float*)d_out;

    cudaFuncSetAttribute(edge_kernel, cudaFuncAttributeMaxDynamicSharedMemorySize, EDGE_SMEM_BYTES);
    cudaFuncSetAttribute(node_kernel, cudaFuncAttributeMaxDynamicSharedMemorySize, NODE_SMEM_BYTES);

    detect_idx_kernel<<<1, 256>>>((const int*)eidx);
    convert_idx_kernel<<<(N_EDGES + 255) / 256, 256>>>(eidx);

    prep_Wc<<<64, 256>>>(W_le, W_e2);
    prep_bc<<<256, 256>>>(W_le, b_e2);
    pack_frags<<<208, 256>>>(W_e1, W_g1, W_g2);
    zero_aggr<<<(N_NODES * D / 4 + 255) / 256, 256>>>();

    edge_kernel<<<N_EDGES / TE, 256, EDGE_SMEM_BYTES>>>(x, edge_attr, b_e1, b_le);
    node_kernel<<<(N_NODES + TN - 1) / TN, 256, NODE_SMEM_BYTES>>>(x, b_g1, ln_g, ln_b, b_g2, out);
}

// round 11
// speedup vs baseline: 8.1140x; 1.3085x over previous
#include <cuda_runtime.h>
#include <cuda_bf16.h>
#include <cuda_fp16.h>
#include <stdint.h>

#define N_NODES 50000
#define N_EDGES 800000
#define D 256
#define F 64
#define LN_EPS 1e-5f
#define TE 64
#define TN 64

// ---------------- device scratch ----------------
__device__ float g_Wc[D * D];            // fp32 (W_le @ W_e2), [n][k]
__device__ float g_bc[D];                // W_le @ b_e2
// fragment-packed fp16 weights (hi only): [k16-slice][ntile(32)][lane(32)] = {h0,h1}
__device__ uint2 g_We1_f[4 * 1024];      // K=64  -> 4 slices
__device__ uint2 g_Wc_f[16 * 1024];      // K=256 -> 16 slices
__device__ uint2 g_Wg1_f[16 * 1024];
__device__ uint2 g_Wg2_f[16 * 1024];
__device__ __align__(16) float g_aggr[(size_t)N_NODES * D];
__device__ int g_idx_is64;
__device__ int g_srcs[N_EDGES], g_dsts[N_EDGES];

// ---------------- low-level helpers ----------------
__device__ __forceinline__ void red_add_v4(float* p, float4 v) {
    asm volatile("red.global.add.v4.f32 [%0], {%1,%2,%3,%4};"
                 :: "l"(p), "f"(v.x), "f"(v.y), "f"(v.z), "f"(v.w) : "memory");
}
__device__ __forceinline__ uint32_t smem_u32(const void* p) {
    return (uint32_t)__cvta_generic_to_shared(p);
}
__device__ __forceinline__ void cpasync16(uint32_t dst, const void* src) {
    asm volatile("cp.async.cg.shared.global [%0], [%1], 16;" :: "r"(dst), "l"(src));
}
__device__ __forceinline__ void cp_commit() { asm volatile("cp.async.commit_group;"); }
__device__ __forceinline__ void cp_wait0()  { asm volatile("cp.async.wait_group 0;"); }

__device__ __forceinline__ void ldsm4(uint32_t* r, uint32_t addr) {
    asm volatile("ldmatrix.sync.aligned.m8n8.x4.shared.b16 {%0,%1,%2,%3}, [%4];"
                 : "=r"(r[0]), "=r"(r[1]), "=r"(r[2]), "=r"(r[3]) : "r"(addr));
}
__device__ __forceinline__ void mma_f16(float* c,
    uint32_t a0, uint32_t a1, uint32_t a2, uint32_t a3, uint32_t b0, uint32_t b1) {
    asm volatile("mma.sync.aligned.m16n8k16.row.col.f32.f16.f16.f32 "
                 "{%0,%1,%2,%3}, {%4,%5,%6,%7}, {%8,%9}, {%0,%1,%2,%3};"
                 : "+f"(c[0]), "+f"(c[1]), "+f"(c[2]), "+f"(c[3])
                 : "r"(a0), "r"(a1), "r"(a2), "r"(a3), "r"(b0), "r"(b1));
}
// fp16 hi/lo split of two fp32 values, packed
__device__ __forceinline__ void splitpack(float a, float b, uint32_t& hi, uint32_t& lo) {
    __half ha = __float2half_rn(a), hb = __float2half_rn(b);
    __half la = __float2half_rn(a - __half2float(ha));
    __half lb = __float2half_rn(b - __half2float(hb));
    hi = (uint32_t)__half_as_ushort(ha) | ((uint32_t)__half_as_ushort(hb) << 16);
    lo = (uint32_t)__half_as_ushort(la) | ((uint32_t)__half_as_ushort(lb) << 16);
}
__device__ __forceinline__ uint32_t pack_f16hi(float a, float b) {
    return (uint32_t)__half_as_ushort(__float2half_rn(a)) |
           ((uint32_t)__half_as_ushort(__float2half_rn(b)) << 16);
}

// contiguous 16KB chunk (2 k16-slices, hi-only) of fragment-packed B -> smem
__device__ __forceinline__ void prefetch_chunk(const uint2* __restrict__ gsrc,
                                               uint32_t b_base, int tid) {
    const uint4* g4 = (const uint4*)gsrc;
    #pragma unroll
    for (int t = 0; t < 4; t++) {
        int i = tid + t * 256;          // 1024 x 16B = 16 KB
        cpasync16(b_base + (uint32_t)i * 16, g4 + i);
    }
    cp_commit();
}

// single-pass 32-k chunk: warp tile 32x64, A hi fp16 from smem (stride 264), B hi-only
__device__ __forceinline__ void gemm_chunk1(float acc[2][8][4],
    uint32_t ah_u, const uint2* __restrict__ B,
    int k0base, int mg, int ng, int lane)
{
    #pragma unroll
    for (int s = 0; s < 2; s++) {
        uint32_t ahi[2][4];
        int col = k0base + s * 16 + ((lane >> 4) << 3);
        #pragma unroll
        for (int mt = 0; mt < 2; mt++) {
            int row = mg * 32 + mt * 16 + (lane & 15);
            ldsm4(ahi[mt], ah_u + (uint32_t)(row * 264 + col) * 2);
        }
        #pragma unroll
        for (int ni = 0; ni < 8; ni++) {
            uint2 f = B[(s * 32 + ng * 8 + ni) * 32 + lane];
            #pragma unroll
            for (int mt = 0; mt < 2; mt++)
                mma_f16(acc[mt][ni], ahi[mt][0], ahi[mt][1], ahi[mt][2], ahi[mt][3], f.x, f.y);
        }
    }
}

// two-pass version (A hi+lo), node kernel only
__device__ __forceinline__ void gemm_chunk2(float acc[2][8][4],
    uint32_t ah_u, uint32_t al_u, const uint2* __restrict__ B,
    int k0base, int mg, int ng, int lane)
{
    #pragma unroll
    for (int s = 0; s < 2; s++) {
        uint32_t ahi[2][4], alo[2][4];
        int col = k0base + s * 16 + ((lane >> 4) << 3);
        #pragma unroll
        for (int mt = 0; mt < 2; mt++) {
            int row = mg * 32 + mt * 16 + (lane & 15);
            ldsm4(ahi[mt], ah_u + (uint32_t)(row * 264 + col) * 2);
            ldsm4(alo[mt], al_u + (uint32_t)(row * 264 + col) * 2);
        }
        #pragma unroll
        for (int ni = 0; ni < 8; ni++) {
            uint2 f = B[(s * 32 + ng * 8 + ni) * 32 + lane];
            #pragma unroll
            for (int mt = 0; mt < 2; mt++) {
                mma_f16(acc[mt][ni], ahi[mt][0], ahi[mt][1], ahi[mt][2], ahi[mt][3], f.x, f.y);
                mma_f16(acc[mt][ni], alo[mt][0], alo[mt][1], alo[mt][2], alo[mt][3], f.x, f.y);
            }
        }
    }
}

// ---------------- index handling (proven) ----------------
__global__ void detect_idx_kernel(const int* __restrict__ p) {
    __shared__ int acc[256];
    int t = threadIdx.x;
    int v = 0;
    #pragma unroll
    for (int i = 0; i < 4; i++) v |= p[(t * 4 + i) * 2 + 1];
    acc[t] = v;
    __syncthreads();
    for (int s = 128; s; s >>= 1) { if (t < s) acc[t] |= acc[t + s]; __syncthreads(); }
    if (t == 0) g_idx_is64 = (acc[0] == 0) ? 1 : 0;
}
__global__ void convert_idx_kernel(const void* __restrict__ eidx) {
    int i = blockIdx.x * blockDim.x + threadIdx.x;
    if (i >= N_EDGES) return;
    int s, d;
    if (g_idx_is64) {
        const long long* p = (const long long*)eidx;
        s = (int)p[i]; d = (int)p[(size_t)N_EDGES + i];
    } else {
        const int* p = (const int*)eidx;
        s = p[i]; d = p[N_EDGES + i];
    }
    g_srcs[i] = min(max(s, 0), N_NODES - 1);
    g_dsts[i] = min(max(d, 0), N_NODES - 1);
}

// ---------------- prep kernels ----------------
__global__ void prep_Wc(const float* __restrict__ W_le, const float* __restrict__ W_e2) {
    __shared__ float wle[4][256];
    int b = blockIdx.x, t = threadIdx.x;       // 64 blocks
    #pragma unroll
    for (int r = 0; r < 4; r++) wle[r][t] = W_le[(b * 4 + r) * 256 + t];
    __syncthreads();
    float a0 = 0, a1 = 0, a2 = 0, a3 = 0;
    #pragma unroll 4
    for (int j = 0; j < 256; j++) {
        float w = W_e2[j * 256 + t];
        a0 += wle[0][j] * w; a1 += wle[1][j] * w;
        a2 += wle[2][j] * w; a3 += wle[3][j] * w;
    }
    g_Wc[(b * 4 + 0) * 256 + t] = a0;
    g_Wc[(b * 4 + 1) * 256 + t] = a1;
    g_Wc[(b * 4 + 2) * 256 + t] = a2;
    g_Wc[(b * 4 + 3) * 256 + t] = a3;
}
__global__ void prep_bc(const float* __restrict__ W_le, const float* __restrict__ b_e2) {
    __shared__ float red[256];
    int d = blockIdx.x, t = threadIdx.x;       // 256 blocks
    red[t] = W_le[d * 256 + t] * b_e2[t];
    __syncthreads();
    for (int s = 128; s; s >>= 1) { if (t < s) red[t] += red[t + s]; __syncthreads(); }
    if (t == 0) g_bc[d] = red[0];
}
// pack all weights into mma-fragment order (fp16 hi only)
__global__ void pack_frags(const float* __restrict__ We1,
                           const float* __restrict__ Wg1,
                           const float* __restrict__ Wg2) {
    int id = blockIdx.x * 256 + threadIdx.x;     // 53248 total
    const float* W; uint2* dst; int K, rel;
    if (id < 4096)       { W = We1;  dst = g_We1_f; K = 64;  rel = id; }
    else if (id < 20480) { W = g_Wc; dst = g_Wc_f;  K = 256; rel = id - 4096; }
    else if (id < 36864) { W = Wg1;  dst = g_Wg1_f; K = 256; rel = id - 20480; }
    else                 { W = Wg2;  dst = g_Wg2_f; K = 256; rel = id - 36864; }
    int slice = rel >> 10, idx = rel & 1023, nt = idx >> 5, lane = idx & 31;
    int nr = lane >> 2, kq = lane & 3;
    int n = nt * 8 + nr, k0 = slice * 16 + kq * 2;
    uint32_t h0 = pack_f16hi(W[n * K + k0],     W[n * K + k0 + 1]);
    uint32_t h1 = pack_f16hi(W[n * K + k0 + 8], W[n * K + k0 + 9]);
    dst[rel] = make_uint2(h0, h1);
}
__global__ void zero_aggr() {
    size_t i = (size_t)blockIdx.x * blockDim.x + threadIdx.x;
    if (i < (size_t)N_NODES * D / 4)
        ((float4*)g_aggr)[i] = make_float4(0.f, 0.f, 0.f, 0.f);
}

// ---------------- edge kernel (64 edges/block, 1-pass fp16, 2 CTAs/SM) ----------------
#define E_AH   0           // fp16 [64][264] = 33792
#define E_B    33792       // 2 x 16384
#define E_SML  66560       // pol 256 | srcs 256 | dsts 256 | bcs 1024 | bls 1024 | be1s 1024
#define EDGE_SMEM_BYTES 70656
#define EMB_STRIDE 260     // fp32 row stride for emb staging (1040B pitch, 16B-aligned)

__global__ __launch_bounds__(256, 2) void edge_kernel(
    const float* __restrict__ x,
    const float* __restrict__ edge_attr,
    const float* __restrict__ b_e1,
    const float* __restrict__ b_le)
{
    extern __shared__ char smem[];
    __half* Ah = (__half*)(smem + E_AH);
    uint2* Bbuf = (uint2*)(smem + E_B);
    float* pol  = (float*)(smem + E_SML);
    int*   srcs = (int*)(smem + E_SML + 256);
    int*   dsts = (int*)(smem + E_SML + 512);
    float* bcs  = (float*)(smem + E_SML + 768);
    float* bls  = (float*)(smem + E_SML + 1792);
    float* be1s = (float*)(smem + E_SML + 2816);

    const int tid  = threadIdx.x;
    const int lane = tid & 31;
    const int warp = tid >> 5;
    const int mg   = warp >> 2;     // 0..1 (row group of 32)
    const int ng   = warp & 3;      // 0..3 (col group of 64)
    const int nr   = lane >> 2, kq = lane & 3;
    const int e0   = blockIdx.x * TE;
    const uint32_t ah_u = smem_u32(Ah);
    const uint32_t bbase = smem_u32(smem + E_B);

    prefetch_chunk(g_We1_f, bbase, tid);          // GEMM1 chunk0 -> buf0

    // stage raw (fp16 hi) into A cols 0..63
    #pragma unroll
    for (int t = 0; t < 16; t++) {
        int i = tid + t * 256;          // 64*64
        int e = i >> 6, k = i & 63;
        float v = edge_attr[(size_t)(e0 + e) * 65 + 1 + k];
        Ah[e * 264 + k] = __float2half_rn(v);
    }
    if (tid < TE) {
        float p = edge_attr[(size_t)(e0 + tid) * 65];
        pol[tid] = fminf(fmaxf(p, 0.f), 1.f) + 0.01f;
        srcs[tid] = g_srcs[e0 + tid];
        dsts[tid] = g_dsts[e0 + tid];
    }
    bcs[tid]  = g_bc[tid];
    bls[tid]  = b_le[tid];
    be1s[tid] = b_e1[tid];

    float acc[2][8][4];
    #pragma unroll
    for (int a = 0; a < 2; a++)
        #pragma unroll
        for (int b = 0; b < 8; b++)
            #pragma unroll
            for (int c = 0; c < 4; c++) acc[a][b][c] = 0.f;

    // ---- GEMM1: h1 = raw @ We1^T (K=64, 2 chunks) ----
    #pragma unroll
    for (int kc = 0; kc < 2; kc++) {
        cp_wait0();
        __syncthreads();
        if (kc == 0) prefetch_chunk(g_We1_f + 2048, bbase + 16384, tid);
        else         prefetch_chunk(g_Wc_f, bbase, tid);        // GEMM2 chunk0 -> buf0
        gemm_chunk1(acc, ah_u, Bbuf + (kc & 1) * 2048, kc * 32, mg, ng, lane);
    }
    __syncthreads();   // all raw reads done before overwrite

    // ---- h1 = relu(acc + b_e1), fp16, store back into A (cols = GEMM2 k) ----
    #pragma unroll
    for (int mt = 0; mt < 2; mt++) {
        int r0 = mg * 32 + mt * 16 + nr, r1 = r0 + 8;
        #pragma unroll
        for (int ni = 0; ni < 8; ni++) {
            int c = ng * 64 + ni * 8 + kq * 2;
            float2 b = *(const float2*)&be1s[c];
            float v0 = fmaxf(acc[mt][ni][0] + b.x, 0.f);
            float v1 = fmaxf(acc[mt][ni][1] + b.y, 0.f);
            float v2 = fmaxf(acc[mt][ni][2] + b.x, 0.f);
            float v3 = fmaxf(acc[mt][ni][3] + b.y, 0.f);
            *(uint32_t*)&Ah[r0 * 264 + c] = pack_f16hi(v0, v1);
            *(uint32_t*)&Ah[r1 * 264 + c] = pack_f16hi(v2, v3);
            acc[mt][ni][0] = acc[mt][ni][1] = acc[mt][ni][2] = acc[mt][ni][3] = 0.f;
        }
    }

    // ---- GEMM2: h2 = h1 @ Wc^T (K=256, 8 chunks, single stream) ----
    #pragma unroll 1
    for (int kc = 0; kc < 8; kc++) {
        cp_wait0();
        __syncthreads();
        if (kc < 7)
            prefetch_chunk(g_Wc_f + (kc + 1) * 2048, bbase + ((kc + 1) & 1) * 16384, tid);
        gemm_chunk1(acc, ah_u, Bbuf + (kc & 1) * 2048, kc * 32, mg, ng, lane);
    }
    __syncthreads();   // A+B reads done; emb may alias the whole region

    // ---- epilogue: emb = pol*(h2 + bc) + bl -> smem (aliases A+B, stride 260) ----
    float* emb = (float*)smem;     // [64][EMB_STRIDE] = 66560 B <= 66560 B
    #pragma unroll
    for (int mt = 0; mt < 2; mt++) {
        int r0 = mg * 32 + mt * 16 + nr, r1 = r0 + 8;
        float p0 = pol[r0], p1 = pol[r1];
        #pragma unroll
        for (int ni = 0; ni < 8; ni++) {
            int c = ng * 64 + ni * 8 + kq * 2;
            float2 bcv = *(const float2*)&bcs[c];
            float2 blv = *(const float2*)&bls[c];
            *(float2*)&emb[r0 * EMB_STRIDE + c] =
                make_float2(p0 * (acc[mt][ni][0] + bcv.x) + blv.x,
                            p0 * (acc[mt][ni][1] + bcv.y) + blv.y);
            *(float2*)&emb[r1 * EMB_STRIDE + c] =
                make_float2(p1 * (acc[mt][ni][2] + bcv.x) + blv.x,
                            p1 * (acc[mt][ni][3] + bcv.y) + blv.y);
        }
    }
    __syncthreads();

    // ---- gather x[src], msg = relu(x+emb), scatter-add ----
    #pragma unroll
    for (int it = 0; it < 8; it++) {
        int r = it * 8 + warp;
        int si = srcs[r], di = dsts[r];
        const float4* xp = (const float4*)(x + (size_t)si * D);
        float* ap = &g_aggr[(size_t)di * D];
        #pragma unroll
        for (int seg = 0; seg < 2; seg++) {
            int c4 = lane + seg * 32;
            float4 ee = *(const float4*)&emb[r * EMB_STRIDE + c4 * 4];
            float4 xv = xp[c4];
            float4 m;
            m.x = fmaxf(xv.x + ee.x, 0.f);
            m.y = fmaxf(xv.y + ee.y, 0.f);
            m.z = fmaxf(xv.z + ee.z, 0.f);
            m.w = fmaxf(xv.w + ee.w, 0.f);
            red_add_v4(ap + c4 * 4, m);
        }
    }
}

// ---------------- node kernel (64 nodes/block, 2-pass, 2 CTAs/SM) ----------------
#define N_AH   0
#define N_AL   33792
#define N_B    67584       // 2 x 16384
#define N_PS   100352      // float2 ps[64][4] = 2048
#define N_SML  102400      // bg1 | lng | lnb | bg2 (4 x 1024)
#define NODE_SMEM_BYTES 106496

__global__ __launch_bounds__(256, 2) void node_kernel(
    const float* __restrict__ x,
    const float* __restrict__ b_g1,
    const float* __restrict__ ln_g,
    const float* __restrict__ ln_b,
    const float* __restrict__ b_g2,
    float* __restrict__ out)
{
    extern __shared__ char smem[];
    __half* Ah = (__half*)(smem + N_AH);
    __half* Al = (__half*)(smem + N_AL);
    uint2* Bbuf = (uint2*)(smem + N_B);
    float2* ps  = (float2*)(smem + N_PS);    // [64 rows][4 ngroups]
    float* bg1 = (float*)(smem + N_SML);
    float* lng = (float*)(smem + N_SML + 1024);
    float* lnb = (float*)(smem + N_SML + 2048);
    float* bg2 = (float*)(smem + N_SML + 3072);

    const int tid  = threadIdx.x;
    const int lane = tid & 31;
    const int warp = tid >> 5;
    const int mg   = warp >> 2;
    const int ng   = warp & 3;
    const int nr   = lane >> 2, kq = lane & 3;
    const int n0   = blockIdx.x * TN;
    const uint32_t ah_u = smem_u32(Ah), al_u = smem_u32(Al);
    const uint32_t bbase = smem_u32(smem + N_B);

    prefetch_chunk(g_Wg1_f, bbase, tid);

    // stage xin = x + aggr, split
    for (int i = tid; i < TN * D; i += 256) {
        int n = i >> 8, d = i & 255;
        int g = n0 + n;
        float v = 0.f;
        if (g < N_NODES) v = x[(size_t)g * D + d] + g_aggr[(size_t)g * D + d];
        __half h = __float2half_rn(v);
        Ah[n * 264 + d] = h;
        Al[n * 264 + d] = __float2half_rn(v - __half2float(h));
    }
    bg1[tid] = b_g1[tid];
    lng[tid] = ln_g[tid];
    lnb[tid] = ln_b[tid];
    bg2[tid] = b_g2[tid];

    float acc[2][8][4];
    #pragma unroll
    for (int a = 0; a < 2; a++)
        #pragma unroll
        for (int b = 0; b < 8; b++)
            #pragma unroll
            for (int c = 0; c < 4; c++) acc[a][b][c] = 0.f;

    // ---- GEMM1 ----
    #pragma unroll 1
    for (int kc = 0; kc < 8; kc++) {
        cp_wait0();
        __syncthreads();
        if (kc < 7) prefetch_chunk(g_Wg1_f + (kc + 1) * 2048, bbase + ((kc + 1) & 1) * 16384, tid);
        else        prefetch_chunk(g_Wg2_f, bbase, tid);       // chain into GEMM2
        gemm_chunk2(acc, ah_u, al_u, Bbuf + (kc & 1) * 2048, kc * 32, mg, ng, lane);
    }

    // ---- bias + partial LN stats (per-warp 64-col partials) ----
    #pragma unroll
    for (int mt = 0; mt < 2; mt++) {
        float sl = 0.f, ql = 0.f, sh = 0.f, qh = 0.f;
        #pragma unroll
        for (int ni = 0; ni < 8; ni++) {
            int c = ng * 64 + ni * 8 + kq * 2;
            float2 b = *(const float2*)&bg1[c];
            float v0 = acc[mt][ni][0] + b.x, v1 = acc[mt][ni][1] + b.y;
            float v2 = acc[mt][ni][2] + b.x, v3 = acc[mt][ni][3] + b.y;
            acc[mt][ni][0] = v0; acc[mt][ni][1] = v1;
            acc[mt][ni][2] = v2; acc[mt][ni][3] = v3;
            sl += v0 + v1; ql += v0 * v0 + v1 * v1;
            sh += v2 + v3; qh += v2 * v2 + v3 * v3;
        }
        #pragma unroll
        for (int off = 1; off <= 2; off <<= 1) {
            sl += __shfl_xor_sync(0xffffffffu, sl, off);
            ql += __shfl_xor_sync(0xffffffffu, ql, off);
            sh += __shfl_xor_sync(0xffffffffu, sh, off);
            qh += __shfl_xor_sync(0xffffffffu, qh, off);
        }
        if (kq == 0) {
            int r0 = mg * 32 + mt * 16 + nr;
            ps[r0 * 4 + ng]       = make_float2(sl, ql);
            ps[(r0 + 8) * 4 + ng] = make_float2(sh, qh);
        }
    }
    __syncthreads();

    // full stats per row, normalize + relu + split -> A (overwrites xin)
    float mu[2][2], rs[2][2];
    #pragma unroll
    for (int mt = 0; mt < 2; mt++) {
        int r0 = mg * 32 + mt * 16 + nr;
        #pragma unroll
        for (int h = 0; h < 2; h++) {
            float s = 0.f, q = 0.f;
            #pragma unroll
            for (int g = 0; g < 4; g++) {
                float2 p = ps[(r0 + h * 8) * 4 + g];
                s += p.x; q += p.y;
            }
            float m = s * (1.f / D);
            float v = q * (1.f / D) - m * m;
            mu[mt][h] = m;
            rs[mt][h] = rsqrtf(v + LN_EPS);
        }
    }
    #pragma unroll
    for (int mt = 0; mt < 2; mt++) {
        int r0 = mg * 32 + mt * 16 + nr, r1 = r0 + 8;
        #pragma unroll
        for (int ni = 0; ni < 8; ni++) {
            int c = ng * 64 + ni * 8 + kq * 2;
            float2 g = *(const float2*)&lng[c];
            float2 bb = *(const float2*)&lnb[c];
            float v0 = fmaxf((acc[mt][ni][0] - mu[mt][0]) * rs[mt][0] * g.x + bb.x, 0.f);
            float v1 = fmaxf((acc[mt][ni][1] - mu[mt][0]) * rs[mt][0] * g.y + bb.y, 0.f);
            float v2 = fmaxf((acc[mt][ni][2] - mu[mt][1]) * rs[mt][1] * g.x + bb.x, 0.f);
            float v3 = fmaxf((acc[mt][ni][3] - mu[mt][1]) * rs[mt][1] * g.y + bb.y, 0.f);
            uint32_t hi, lo;
            splitpack(v0, v1, hi, lo);
            *(uint32_t*)&Ah[r0 * 264 + c] = hi;
            *(uint32_t*)&Al[r0 * 264 + c] = lo;
            splitpack(v2, v3, hi, lo);
            *(uint32_t*)&Ah[r1 * 264 + c] = hi;
            *(uint32_t*)&Al[r1 * 264 + c] = lo;
            acc[mt][ni][0] = acc[mt][ni][1] = acc[mt][ni][2] = acc[mt][ni][3] = 0.f;
        }
    }

    // ---- GEMM2 (first sync inside loop orders the A stores above) ----
    #pragma unroll 1
    for (int kc = 0; kc < 8; kc++) {
        cp_wait0();
        __syncthreads();
        if (kc < 7) prefetch_chunk(g_Wg2_f + (kc + 1) * 2048, bbase + ((kc + 1) & 1) * 16384, tid);
        gemm_chunk2(acc, ah_u, al_u, Bbuf + (kc & 1) * 2048, kc * 32, mg, ng, lane);
    }

    // ---- epilogue: + b_g2 -> out ----
    #pragma unroll
    for (int mt = 0; mt < 2; mt++) {
        int r0 = mg * 32 + mt * 16 + nr, r1 = r0 + 8;
        int gr0 = n0 + r0, gr1 = n0 + r1;
        #pragma unroll
        for (int ni = 0; ni < 8; ni++) {
            int c = ng * 64 + ni * 8 + kq * 2;
            float2 b = *(const float2*)&bg2[c];
            if (gr0 < N_NODES)
                *(float2*)&out[(size_t)gr0 * D + c] =
                    make_float2(acc[mt][ni][0] + b.x, acc[mt][ni][1] + b.y);
            if (gr1 < N_NODES)
                *(float2*)&out[(size_t)gr1 * D + c] =
                    make_float2(acc[mt][ni][2] + b.x, acc[mt][ni][3] + b.y);
        }
    }
}

// ---------------- launch ----------------
extern "C" void kernel_launch(void* const* d_in, const int* in_sizes, int n_in,
                              void* d_out, int out_size)
{
    const float* x         = (const float*)d_in[0];
    const void*  eidx      = d_in[1];
    const float* edge_attr = (const float*)d_in[2];
    const float* W_e1      = (const float*)d_in[3];
    const float* b_e1      = (const float*)d_in[4];
    const float* W_e2      = (const float*)d_in[5];
    const float* b_e2      = (const float*)d_in[6];
    const float* W_le      = (const float*)d_in[7];
    const float* b_le      = (const float*)d_in[8];
    const float* W_g1      = (const float*)d_in[9];
    const float* b_g1      = (const float*)d_in[10];
    const float* ln_g      = (const float*)d_in[11];
    const float* ln_b      = (const float*)d_in[12];
    const float* W_g2      = (const float*)d_in[13];
    const float* b_g2      = (const float*)d_in[14];
    float*       out       = (float*)d_out;

    cudaFuncSetAttribute(edge_kernel, cudaFuncAttributeMaxDynamicSharedMemorySize, EDGE_SMEM_BYTES);
    cudaFuncSetAttribute(node_kernel, cudaFuncAttributeMaxDynamicSharedMemorySize, NODE_SMEM_BYTES);

    detect_idx_kernel<<<1, 256>>>((const int*)eidx);
    convert_idx_kernel<<<(N_EDGES + 255) / 256, 256>>>(eidx);

    prep_Wc<<<64, 256>>>(W_le, W_e2);
    prep_bc<<<256, 256>>>(W_le, b_e2);
    pack_frags<<<208, 256>>>(W_e1, W_g1, W_g2);
    zero_aggr<<<(N_NODES * D / 4 + 255) / 256, 256>>>();

    edge_kernel<<<N_EDGES / TE, 256, EDGE_SMEM_BYTES>>>(x, edge_attr, b_e1, b_le);
    node_kernel<<<(N_NODES + TN - 1) / TN, 256, NODE_SMEM_BYTES>>>(x, b_g1, ln_g, ln_b, b_g2, out);
}